// round 13
// baseline (speedup 1.0000x reference)
#include <cuda_runtime.h>
#include <math.h>

#define Bn   4
#define HWp  16384
#define LSEQ 16384
#define CH   256
#define NCH  64

// ---------------- tf32 mma helpers ----------------
__device__ __forceinline__ unsigned tf32cvt(float v){
    unsigned r; asm("cvt.rna.tf32.f32 %0, %1;" : "=r"(r) : "f"(v)); return r;
}
__device__ __forceinline__ void mma_tf32(float* d, unsigned a0, unsigned a1, unsigned a2, unsigned a3,
                                         unsigned b0, unsigned b1){
    asm("mma.sync.aligned.m16n8k8.row.col.f32.tf32.tf32.f32 "
        "{%0,%1,%2,%3}, {%4,%5,%6,%7}, {%8,%9}, {%0,%1,%2,%3};"
        : "+f"(d[0]), "+f"(d[1]), "+f"(d[2]), "+f"(d[3])
        : "r"(a0), "r"(a1), "r"(a2), "r"(a3), "r"(b0), "r"(b1));
}

// ---------------- scratch ----------------
__device__ float g_xT[Bn*HWp*64];        // [b][pix][c]
__device__ float g_rawoff[Bn*10*HWp];    // offset conv out, [b][co][pix]
__device__ float g_ostats[Bn*5*2];
__device__ float g_ynew[Bn*9*HWp];       // [b][k][pix]
__device__ float g_dt[Bn*18*LSEQ];
__device__ float g_xi[Bn*18*LSEQ];
__device__ float g_gate[Bn*18*LSEQ];     // silu(z)
__device__ float g_Bsc[Bn*16*LSEQ];
__device__ float g_Csc[Bn*16*LSEQ];
__device__ float g_P[Bn*NCH*288];
__device__ float g_Q[Bn*NCH*288];
__device__ float g_hinit[Bn*NCH*288];
__device__ unsigned g_wAf[9*64*64];      // deform conv A, mma fragment order
__device__ unsigned g_wCf[9*8*128];      // offset conv A, mma fragment order
__device__ float g_outraw[Bn*64*HWp];
__device__ float g_fstats[Bn*16*2];

__device__ __forceinline__ float softplusf(float x){
    return x > 20.f ? x : log1pf(expf(x));
}
__device__ __forceinline__ float siluf(float x){
    return x / (1.f + expf(-x));
}

// ---------------- prep: transpose x + zero stats + weight tf32 conversions ----------------
__global__ void kPrep(const float* __restrict__ x, const float* __restrict__ dscw,
                      const float* __restrict__ offw){
    __shared__ float tile[32][33];
    int b = blockIdx.z, c0 = blockIdx.y*32, p0 = blockIdx.x*32;
    int bid = (blockIdx.z*gridDim.y + blockIdx.y)*gridDim.x + blockIdx.x;
    int gtid = bid*256 + threadIdx.y*32 + threadIdx.x;

    if (gtid < 36864){
        int k = gtid >> 12;
        int rem = gtid & 4095;
        int ctq = rem >> 10;
        int rem2 = rem & 1023;
        int ks = rem2 >> 7;
        int r = rem2 & 127;
        int lane = r >> 2, q = r & 3;
        int gID = lane >> 2, tig = lane & 3;
        int co = ctq*16 + gID + ((q & 1) << 3);
        int ci = ks*8 + tig + ((q >> 1) << 2);
        g_wAf[gtid] = tf32cvt(dscw[(co*64 + ci)*9 + k]);
    }
    if (gtid >= 40960 && gtid < 40960+9216){
        int idx = gtid - 40960;
        int tap = idx >> 10; int rem = idx & 1023;
        int ks = rem >> 7;   int r = rem & 127;
        int lane = r >> 2,   q = r & 3;
        int gID = lane >> 2, tig = lane & 3;
        int co = gID + 8*(q & 1);
        int ci = ks*8 + tig + 4*(q >> 1);
        int dy = tap/3, dx = tap - dy*3;
        float v = (co < 10) ? offw[((co*64+ci)*3 + dy)*3 + dx] : 0.f;
        g_wCf[idx] = tf32cvt(v);
    }
    if (gtid >= 65536 && gtid < 65536+40)  g_ostats[gtid-65536] = 0.f;
    if (gtid >= 131072 && gtid < 131072+128) g_fstats[gtid-131072] = 0.f;

    for (int i = threadIdx.y; i < 32; i += 8)
        tile[i][threadIdx.x] = x[(size_t)(b*64 + c0 + i)*HWp + p0 + threadIdx.x];
    __syncthreads();
    for (int i = threadIdx.y; i < 32; i += 8)
        g_xT[(size_t)(b*HWp + p0 + i)*64 + c0 + threadIdx.x] = tile[threadIdx.x][i];
}

// ---------------- offset conv 3x3 64->10 via tf32 mma (implicit im2col) ----------------
#define CONVM_SMEM (390*68*4)
__global__ void __launch_bounds__(256) kConvM(const float* __restrict__ offb){
    extern __shared__ unsigned su[];
    unsigned* sV = su;            // [dy*130+jp][68]
    int h = blockIdx.x, b = blockIdx.y, t = threadIdx.x;
    int wid = t >> 5, lane = t & 31, gID = lane >> 2, tig = lane & 3;
    int n0 = wid*16;

    // incremental fill: r = dy*130+jp walks +16, c4 fixed per thread
    {
        int c4 = t & 15;
        int r = t >> 4;             // [0,16)
        int jp = r, dy = 0;
        while (r < 390){
            int gh = h - 1 + dy, gw = jp - 1;
            float4 v = make_float4(0.f, 0.f, 0.f, 0.f);
            if (gh >= 0 && gh < 128 && gw >= 0 && gw < 128)
                v = *(const float4*)&g_xT[((size_t)b*HWp + gh*128 + gw)*64 + c4*4];
            uint4 tv;
            tv.x = tf32cvt(v.x); tv.y = tf32cvt(v.y);
            tv.z = tf32cvt(v.z); tv.w = tf32cvt(v.w);
            *(uint4*)&sV[r*68 + c4*4] = tv;
            r += 16; jp += 16;
            if (jp >= 130){ jp -= 130; dy++; }
        }
    }
    __syncthreads();

    float acc[2][4];
    #pragma unroll
    for (int nt = 0; nt < 2; nt++)
        #pragma unroll
        for (int p = 0; p < 4; p++) acc[nt][p] = 0.f;

    #pragma unroll
    for (int tap = 0; tap < 9; tap++){
        int dy = tap/3, dx = tap - dy*3;
        int vbase = dy*130 + dx;
        #pragma unroll
        for (int ks = 0; ks < 8; ks++){
            int kk = ks*8;
            uint4 f = *(const uint4*)&g_wCf[((tap*8 + ks) << 7) + (lane << 2)];
            #pragma unroll
            for (int nt = 0; nt < 2; nt++){
                int j = n0 + nt*8 + gID;
                unsigned b0 = sV[(vbase + j)*68 + kk + tig];
                unsigned b1 = sV[(vbase + j)*68 + kk + tig + 4];
                mma_tf32(acc[nt], f.x, f.y, f.z, f.w, b0, b1);
            }
        }
    }

    int co0 = gID, co1 = gID + 8;
    float bias0 = offb[co0];
    float bias1 = (gID < 2) ? offb[co1] : 0.f;
    float s0 = 0.f, ss0 = 0.f, s1 = 0.f, ss1 = 0.f;
    #pragma unroll
    for (int nt = 0; nt < 2; nt++){
        float c0 = acc[nt][0] + bias0, c1 = acc[nt][1] + bias0;
        int pix = h*128 + n0 + nt*8 + tig*2;
        *(float2*)&g_rawoff[((size_t)(b*10+co0))*HWp + pix] = make_float2(c0, c1);
        s0 += c0 + c1; ss0 += c0*c0 + c1*c1;
        if (gID < 2){
            float c2 = acc[nt][2] + bias1, c3 = acc[nt][3] + bias1;
            *(float2*)&g_rawoff[((size_t)(b*10+co1))*HWp + pix] = make_float2(c2, c3);
            s1 += c2 + c3; ss1 += c2*c2 + c3*c3;
        }
    }
    #pragma unroll
    for (int m = 1; m <= 4; m <<= 1){
        s0  += __shfl_xor_sync(0xffffffffu, s0,  m);
        ss0 += __shfl_xor_sync(0xffffffffu, ss0, m);
        s1  += __shfl_xor_sync(0xffffffffu, s1,  m);
        ss1 += __shfl_xor_sync(0xffffffffu, ss1, m);
    }
    if (tig == 0 && (gID & 1) == 0){
        int g0 = gID >> 1;
        atomicAdd(&g_ostats[(b*5 + g0)*2    ], s0);
        atomicAdd(&g_ostats[(b*5 + g0)*2 + 1], ss0);
        if (gID == 0){
            atomicAdd(&g_ostats[(b*5 + 4)*2    ], s1);
            atomicAdd(&g_ostats[(b*5 + 4)*2 + 1], ss1);
        }
    }
}

// ---------------- fused: GN+tanh+cumsum+ynew -> front-end GEMVs -> scan pass1 ----------------
__device__ __forceinline__ void comp_tv(int b, int l, const float* sMu, const float* sRs,
                                        const float* __restrict__ gnog,
                                        const float* __restrict__ gnob, float* tv){
    int tt = l & 1, r = l >> 1;
    int w = r & 127, r2 = r >> 7;
    int p = (r2*2 + tt)*128 + w;
    #pragma unroll
    for (int c = 0; c < 9; c++){
        float raw = g_rawoff[((size_t)(b*10+c))*HWp + p];
        float xn = (raw - sMu[c>>1]) * sRs[c>>1] * gnog[c] + gnob[c];
        tv[c] = tanhf(xn);
    }
}

#define FUS_SMEM (19339*4)
__global__ void __launch_bounds__(288) kFused(
        const float* __restrict__ gnog, const float* __restrict__ gnob,
        const float* __restrict__ ipw,  const float* __restrict__ cw,
        const float* __restrict__ cb,   const float* __restrict__ xpw,
        const float* __restrict__ dtw,  const float* __restrict__ dtb,
        const float* __restrict__ Alog){
    extern __shared__ float sm[];
    float* sXP  = sm;            // 259*19
    float* sIPW = sm + 4921;     // 324
    float* sXPW = sm + 5245;     // 594
    float* sCW  = sm + 5839;     // 72
    float* sCB  = sm + 5911;     // 18
    float* sDTW = sm + 5929;     // 18
    float* sDTB = sm + 5947;     // 18
    float* sMu  = sm + 5965;     // 5
    float* sRs  = sm + 5970;     // 5
    float* sDT  = sm + 5975;     // 18*257
    float* sXI  = sm + 10601;    // 18*257
    float* sB   = sm + 15227;    // 16*257
    int b = blockIdx.y, c = blockIdx.x, l0 = c*CH, t = threadIdx.x;

    for (int idx = t; idx < 324; idx += 288) sIPW[idx] = ipw[idx];
    for (int idx = t; idx < 594; idx += 288) sXPW[idx] = xpw[idx];
    if (t < 72) sCW[t] = cw[t];
    if (t < 18){ sCB[t] = cb[t]; sDTW[t] = dtw[t]; sDTB[t] = dtb[t]; }
    if (t < 5){
        float s  = g_ostats[(b*5+t)*2];
        float ss = g_ostats[(b*5+t)*2+1];
        float mu = s * (1.f/32768.f);
        float var = ss * (1.f/32768.f) - mu*mu;
        sMu[t] = mu;
        sRs[t] = rsqrtf(var + 1e-5f);
    }
    __syncthreads();

    if (t < CH){
        int l = l0 + t;
        float tv[9];
        comp_tv(b, l, sMu, sRs, gnog, gnob, tv);

        float cum[9];
        cum[4] = 0.f;
        cum[5] = tv[5]; cum[6] = cum[5]+tv[6]; cum[7] = cum[6]+tv[7]; cum[8] = cum[7]+tv[8];
        cum[3] = tv[3]; cum[2] = cum[3]+tv[2]; cum[1] = cum[2]+tv[1]; cum[0] = cum[1]+tv[0];

        int tt = l & 1, r = l >> 1;
        int w = r & 127, r2 = r >> 7;
        int h = r2*2 + tt, p = h*128 + w;
        #pragma unroll
        for (int k = 0; k < 9; k++)
            g_ynew[((size_t)(b*9+k))*HWp + p] = (float)h + cum[k];

        #pragma unroll
        for (int n = 0; n < 18; n++){
            float v = 0.f;
            #pragma unroll
            for (int m = 0; m < 9; m++) v += tv[m]*sIPW[n*9+m];
            sXP[(t+3)*19 + n] = v;
        }
        #pragma unroll
        for (int n = 0; n < 18; n++){
            float z = 0.f;
            #pragma unroll
            for (int m = 0; m < 9; m++) z += tv[m]*sIPW[(18+n)*9+m];
            g_gate[((size_t)(b*18+n))*LSEQ + l] = siluf(z);
        }
    } else if (t < CH+3){
        int bi = t - CH;
        int l2 = l0 - 3 + bi;
        if (l2 >= 0){
            float tv2[9];
            comp_tv(b, l2, sMu, sRs, gnog, gnob, tv2);
            #pragma unroll
            for (int n = 0; n < 18; n++){
                float v = 0.f;
                #pragma unroll
                for (int m = 0; m < 9; m++) v += tv2[m]*sIPW[n*9+m];
                sXP[bi*19 + n] = v;
            }
        } else {
            #pragma unroll
            for (int n = 0; n < 18; n++) sXP[bi*19 + n] = 0.f;
        }
    }
    __syncthreads();

    if (t < CH){
        int l = l0 + t;
        float xi[18];
        #pragma unroll
        for (int d = 0; d < 18; d++){
            float xc = sCB[d];
            #pragma unroll
            for (int j = 0; j < 4; j++) xc += sCW[d*4+j]*sXP[(t+j)*19 + d];
            xi[d] = siluf(xc);
        }
        float dtr = 0.f;
        #pragma unroll
        for (int d = 0; d < 18; d++) dtr += xi[d]*sXPW[d];
        #pragma unroll
        for (int s = 0; s < 16; s++){
            float bv = 0.f, cv = 0.f;
            #pragma unroll
            for (int d = 0; d < 18; d++){
                bv += xi[d]*sXPW[(1+s)*18 + d];
                cv += xi[d]*sXPW[(17+s)*18 + d];
            }
            sB[s*257 + t] = bv;
            g_Bsc[((size_t)(b*16+s))*LSEQ + l] = bv;
            g_Csc[((size_t)(b*16+s))*LSEQ + l] = cv;
        }
        #pragma unroll
        for (int d = 0; d < 18; d++){
            float a = dtr*sDTW[d] + sDTB[d];
            float dtv = softplusf(a);
            sDT[d*257 + t] = dtv;
            sXI[d*257 + t] = xi[d];
            g_dt[((size_t)(b*18+d))*LSEQ + l] = dtv;
            g_xi[((size_t)(b*18+d))*LSEQ + l] = xi[d];
        }
    }
    __syncthreads();

    int d = t / 16, s = t % 16;
    float a = -expf(Alog[d*16+s]);
    float p = 1.f, q = 0.f;
    for (int i = 0; i < CH; i++){
        float dt = sDT[d*257+i];
        float da = __expf(dt*a);
        q = da*q + dt*sB[s*257+i]*sXI[d*257+i];
        p *= da;
    }
    g_P[(b*NCH+c)*288 + t] = p;
    g_Q[(b*NCH+c)*288 + t] = q;
}

// ---------------- scan pass2: serial carry, t-sliced 18/block ----------------
#define SCAN2_SMEM (2*NCH*18*4)
__global__ void __launch_bounds__(288) kScan2(){
    extern __shared__ float sm[];
    float* sP = sm;            // [c][18]
    float* sQ = sm + NCH*18;
    int b = blockIdx.x, sl = blockIdx.y, t = threadIdx.x;
    int t0 = sl*18;
    for (int idx = t; idx < NCH*18; idx += 288){
        int c = idx/18, tt = idx - c*18;
        sP[idx] = g_P[(b*NCH+c)*288 + t0 + tt];
        sQ[idx] = g_Q[(b*NCH+c)*288 + t0 + tt];
    }
    __syncthreads();
    if (t < 18){
        float h = 0.f;
        #pragma unroll 8
        for (int c = 0; c < NCH; c++){
            g_hinit[(b*NCH+c)*288 + t0 + t] = h;
            h = sP[c*18+t]*h + sQ[c*18+t];
        }
    }
}

// ---------------- fused scan pass3 + deformable conv (py stays in smem) ----------------
// block = (chunk c, b): scan rows 2c,2c+1, then deform both rows.
// smem: [sDT|sXI|sB|sC|sYS (86*257)][sOPW 162][sDP 18][sPY 9*2*132]
// deform phase overlays sV (128*68=8704 words) onto sDT/sXI region after sync.
#define S3D_SMEM ((86*257 + 162 + 18 + 9*2*132)*4)
__global__ void __launch_bounds__(288) kScan3D(const float* __restrict__ Alog, const float* __restrict__ Dp,
                       const float* __restrict__ opw,  const float* __restrict__ altho,
                       const float* __restrict__ dscb){
    extern __shared__ float sm[];
    float* sDT = sm;
    float* sXI = sm + 18*257;
    float* sB  = sm + 36*257;
    float* sC  = sm + 52*257;
    float* sYS = sm + 68*257;
    float* sOPW = sm + 86*257;
    float* sDP  = sm + 86*257 + 162;
    float* sPY  = sm + 86*257 + 180;   // [m*2+rr][132]
    unsigned* sV = (unsigned*)sm;      // overlay for deform phase
    int b = blockIdx.y, c = blockIdx.x, l0 = c*CH, t = threadIdx.x;

    for (int idx = t; idx < 18*CH; idx += 288){
        int dd = idx >> 8, i = idx & 255;
        sDT[dd*257+i] = g_dt[((size_t)(b*18+dd))*LSEQ + l0 + i];
        sXI[dd*257+i] = g_xi[((size_t)(b*18+dd))*LSEQ + l0 + i];
    }
    for (int idx = t; idx < 16*CH; idx += 288){
        int ss = idx >> 8, i = idx & 255;
        sB[ss*257+i] = g_Bsc[((size_t)(b*16+ss))*LSEQ + l0 + i];
        sC[ss*257+i] = g_Csc[((size_t)(b*16+ss))*LSEQ + l0 + i];
    }
    if (t < 162) sOPW[t] = opw[t];
    if (t < 18)  sDP[t]  = Dp[t];
    __syncthreads();

    {
        int d = t / 16, s = t % 16;
        float a = -expf(Alog[d*16+s]);
        float h = g_hinit[(b*NCH+c)*288 + t];
        for (int i = 0; i < CH; i++){
            float dt = sDT[d*257+i];
            float da = __expf(dt*a);
            h = da*h + dt*sB[s*257+i]*sXI[d*257+i];
            float v = h * sC[s*257+i];
            v += __shfl_xor_sync(0xffffffffu, v, 1);
            v += __shfl_xor_sync(0xffffffffu, v, 2);
            v += __shfl_xor_sync(0xffffffffu, v, 4);
            v += __shfl_xor_sync(0xffffffffu, v, 8);
            if ((t & 15) == 0) sYS[d*257+i] = v;
        }
    }
    __syncthreads();

    if (t < CH){
        int l = l0 + t;
        float wgt = fmaxf(softplusf(altho[0]), 0.01f);
        float ym[9];
        #pragma unroll
        for (int m = 0; m < 9; m++) ym[m] = 0.f;
        #pragma unroll
        for (int dd = 0; dd < 18; dd++){
            float yv = (sYS[dd*257+t] + sDP[dd]*sXI[dd*257+t]) * g_gate[((size_t)(b*18+dd))*LSEQ + l];
            #pragma unroll
            for (int m = 0; m < 9; m++) ym[m] += yv * sOPW[m*18+dd];
        }
        int rr = t & 1, w = t >> 1;
        int h2 = c;
        int pix = (h2*2 + rr)*128 + w;
        #pragma unroll
        for (int m = 0; m < 9; m++){
            float py = wgt*ym[m] + g_ynew[((size_t)(b*9+m))*HWp + pix];
            py = fminf(fmaxf(py, 0.f), 127.f);
            sPY[(m*2 + rr)*132 + w] = py;
        }
    }
    __syncthreads();

    // ---- deform phase: rows 2c (rr=0) and 2c+1 (rr=1) ----
    int wid = t >> 5, lane = t & 31;
    int gID = lane >> 2, tig = lane & 3;
    int ctq = wid & 3, ct = ctq*16;
    int pt = (wid >> 2)*64;

    for (int rr = 0; rr < 2; rr++){
        int i = 2*c + rr;
        float acc[8][4];
        #pragma unroll
        for (int nt = 0; nt < 8; nt++)
            #pragma unroll
            for (int p = 0; p < 4; p++) acc[nt][p] = 0.f;

        for (int k = 0; k < 9; k++){
            if (t < 256){
                int p0 = wid*16;
                #pragma unroll
                for (int pp = 0; pp < 16; pp++){
                    int j = p0 + pp;
                    float pyv = sPY[(k*2 + rr)*132 + j];
                    float fy0 = floorf(pyv);
                    int y0 = (int)fy0;
                    float wy = pyv - fy0;
                    float wy0 = 1.f - wy;
                    int y1 = min(y0 + 1, 127);
                    int xc = min(max(j + k - 4, 0), 127);
                    const float* base0 = &g_xT[((size_t)b*HWp + y0*128 + xc)*64];
                    const float* base1 = &g_xT[((size_t)b*HWp + y1*128 + xc)*64];
                    float vL = base0[lane]*wy0    + base1[lane]*wy;
                    float vH = base0[lane+32]*wy0 + base1[lane+32]*wy;
                    sV[j*68 + lane]      = tf32cvt(vL);
                    sV[j*68 + lane + 32] = tf32cvt(vH);
                }
            }
            __syncthreads();
            if (t < 256){
                #pragma unroll
                for (int ks = 0; ks < 8; ks++){
                    int kk = ks*8;
                    uint4 f = *(const uint4*)&g_wAf[((((k*4 + ctq)*8) + ks) << 7) + (lane << 2)];
                    #pragma unroll
                    for (int nt = 0; nt < 8; nt++){
                        int n0 = pt + nt*8;
                        unsigned b0 = sV[(n0+gID)*68 + kk + tig];
                        unsigned b1 = sV[(n0+gID)*68 + kk + tig + 4];
                        mma_tf32(acc[nt], f.x, f.y, f.z, f.w, b0, b1);
                    }
                }
            }
            __syncthreads();
        }

        if (t < 256){
            int co0 = ct + gID, co1 = ct + gID + 8;
            float bias0 = dscb[co0], bias1 = dscb[co1];
            float s0 = 0.f, ss0 = 0.f, s1 = 0.f, ss1 = 0.f;
            #pragma unroll
            for (int nt = 0; nt < 8; nt++){
                float c0 = acc[nt][0] + bias0, c1 = acc[nt][1] + bias0;
                float c2 = acc[nt][2] + bias1, c3 = acc[nt][3] + bias1;
                size_t pix = (size_t)i*128 + pt + nt*8 + tig*2;
                *(float2*)&g_outraw[((size_t)(b*64+co0))*HWp + pix] = make_float2(c0, c1);
                *(float2*)&g_outraw[((size_t)(b*64+co1))*HWp + pix] = make_float2(c2, c3);
                s0 += c0 + c1; ss0 += c0*c0 + c1*c1;
                s1 += c2 + c3; ss1 += c2*c2 + c3*c3;
            }
            #pragma unroll
            for (int m = 1; m <= 8; m <<= 1){
                s0  += __shfl_xor_sync(0xffffffffu, s0,  m);
                ss0 += __shfl_xor_sync(0xffffffffu, ss0, m);
                s1  += __shfl_xor_sync(0xffffffffu, s1,  m);
                ss1 += __shfl_xor_sync(0xffffffffu, ss1, m);
            }
            if ((lane & 15) == 0){
                int g0 = (ct >> 2) + (lane >> 4);
                atomicAdd(&g_fstats[(b*16 + g0)*2    ], s0);
                atomicAdd(&g_fstats[(b*16 + g0)*2 + 1], ss0);
                atomicAdd(&g_fstats[(b*16 + g0 + 2)*2    ], s1);
                atomicAdd(&g_fstats[(b*16 + g0 + 2)*2 + 1], ss1);
            }
        }
    }
}

// ---------------- final GN (float4) ----------------
__global__ void kFinalGN(const float* __restrict__ gng, const float* __restrict__ gnb,
                         float* __restrict__ out){
    int idx4 = blockIdx.x*256 + threadIdx.x;
    int idx = idx4*4;
    int b = idx >> 20;
    int c = (idx >> 14) & 63;
    int g = c >> 2;
    float s  = g_fstats[(b*16+g)*2];
    float ss = g_fstats[(b*16+g)*2+1];
    float mu = s * (1.f/65536.f);
    float var = ss * (1.f/65536.f) - mu*mu;
    float rs = rsqrtf(var + 1e-5f) * gng[c];
    float bb = gnb[c];
    float4 v = *(const float4*)&g_outraw[idx];
    float4 o;
    o.x = (v.x - mu)*rs + bb;
    o.y = (v.y - mu)*rs + bb;
    o.z = (v.z - mu)*rs + bb;
    o.w = (v.w - mu)*rs + bb;
    *(float4*)&out[idx] = o;
}

extern "C" void kernel_launch(void* const* d_in, const int* in_sizes, int n_in,
                              void* d_out, int out_size){
    const float* x     = (const float*)d_in[0];
    const float* offw  = (const float*)d_in[1];
    const float* offb  = (const float*)d_in[2];
    const float* gnog  = (const float*)d_in[3];
    const float* gnob  = (const float*)d_in[4];
    const float* altho = (const float*)d_in[5];
    const float* ipw   = (const float*)d_in[6];
    const float* cw    = (const float*)d_in[7];
    const float* cb    = (const float*)d_in[8];
    const float* xpw   = (const float*)d_in[9];
    const float* dtw   = (const float*)d_in[10];
    const float* dtb   = (const float*)d_in[11];
    const float* Alog  = (const float*)d_in[12];
    const float* Dp    = (const float*)d_in[13];
    const float* opw   = (const float*)d_in[14];
    const float* dscw  = (const float*)d_in[15];
    const float* dscb  = (const float*)d_in[16];
    const float* gng   = (const float*)d_in[17];
    const float* gnb   = (const float*)d_in[18];
    float* out = (float*)d_out;

    cudaFuncSetAttribute(kConvM,  cudaFuncAttributeMaxDynamicSharedMemorySize, CONVM_SMEM);
    cudaFuncSetAttribute(kFused,  cudaFuncAttributeMaxDynamicSharedMemorySize, FUS_SMEM);
    cudaFuncSetAttribute(kScan3D, cudaFuncAttributeMaxDynamicSharedMemorySize, S3D_SMEM);

    kPrep<<<dim3(512, 2, 4), dim3(32, 8)>>>(x, dscw, offw);
    kConvM<<<dim3(128, 4), 256, CONVM_SMEM>>>(offb);
    kFused<<<dim3(NCH, 4), 288, FUS_SMEM>>>(gnog, gnob, ipw, cw, cb, xpw, dtw, dtb, Alog);
    kScan2<<<dim3(4, 16), 288, SCAN2_SMEM>>>();
    kScan3D<<<dim3(NCH, 4), 288, S3D_SMEM>>>(Alog, Dp, opw, altho, dscb);
    kFinalGN<<<4096, 256>>>(gng, gnb, out);
}

// round 14
// speedup vs baseline: 1.2126x; 1.2126x over previous
#include <cuda_runtime.h>
#include <math.h>

#define Bn   4
#define HWp  16384
#define LSEQ 16384
#define CH   256
#define NCH  64

// ---------------- tf32 mma helpers ----------------
__device__ __forceinline__ unsigned tf32cvt(float v){
    unsigned r; asm("cvt.rna.tf32.f32 %0, %1;" : "=r"(r) : "f"(v)); return r;
}
__device__ __forceinline__ void mma_tf32(float* d, unsigned a0, unsigned a1, unsigned a2, unsigned a3,
                                         unsigned b0, unsigned b1){
    asm("mma.sync.aligned.m16n8k8.row.col.f32.tf32.tf32.f32 "
        "{%0,%1,%2,%3}, {%4,%5,%6,%7}, {%8,%9}, {%0,%1,%2,%3};"
        : "+f"(d[0]), "+f"(d[1]), "+f"(d[2]), "+f"(d[3])
        : "r"(a0), "r"(a1), "r"(a2), "r"(a3), "r"(b0), "r"(b1));
}

// ---------------- scratch ----------------
__device__ float g_xT[Bn*HWp*64];        // [b][pix][c]
__device__ float g_rawoff[Bn*10*HWp];    // offset conv out, [b][co][pix]
__device__ float g_ostats[Bn*5*2];
__device__ float g_ynew[Bn*9*HWp];       // [b][k][pix]
__device__ float g_dt[Bn*18*LSEQ];
__device__ float g_xi[Bn*18*LSEQ];
__device__ float g_gate[Bn*18*LSEQ];     // silu(z)
__device__ float g_Bsc[Bn*16*LSEQ];
__device__ float g_Csc[Bn*16*LSEQ];
__device__ float g_P[Bn*NCH*288];
__device__ float g_Q[Bn*NCH*288];
__device__ float g_hinit[Bn*NCH*288];
__device__ float g_py[Bn*9*HWp];         // [b][k][pix]
__device__ unsigned g_wAf[9*64*64];      // deform conv A, mma fragment order
__device__ unsigned g_wCf[9*8*128];      // offset conv A, mma fragment order
__device__ float g_outraw[Bn*64*HWp];
__device__ float g_fstats[Bn*16*2];

__device__ __forceinline__ float softplusf(float x){
    return x > 20.f ? x : log1pf(__expf(x));
}
__device__ __forceinline__ float siluf(float x){
    return __fdividef(x, 1.f + __expf(-x));
}
__device__ __forceinline__ float ftanh(float x){
    float xc = fminf(fmaxf(x, -15.f), 15.f);
    float e = __expf(2.f*xc);
    return __fdividef(e - 1.f, e + 1.f);
}

// ---------------- prep: transpose x + zero stats + weight tf32 conversions ----------------
__global__ void kPrep(const float* __restrict__ x, const float* __restrict__ dscw,
                      const float* __restrict__ offw){
    __shared__ float tile[32][33];
    int b = blockIdx.z, c0 = blockIdx.y*32, p0 = blockIdx.x*32;
    int bid = (blockIdx.z*gridDim.y + blockIdx.y)*gridDim.x + blockIdx.x;
    int gtid = bid*256 + threadIdx.y*32 + threadIdx.x;

    if (gtid < 36864){
        int k = gtid >> 12;
        int rem = gtid & 4095;
        int ctq = rem >> 10;
        int rem2 = rem & 1023;
        int ks = rem2 >> 7;
        int r = rem2 & 127;
        int lane = r >> 2, q = r & 3;
        int gID = lane >> 2, tig = lane & 3;
        int co = ctq*16 + gID + ((q & 1) << 3);
        int ci = ks*8 + tig + ((q >> 1) << 2);
        g_wAf[gtid] = tf32cvt(dscw[(co*64 + ci)*9 + k]);
    }
    if (gtid >= 40960 && gtid < 40960+9216){
        int idx = gtid - 40960;
        int tap = idx >> 10; int rem = idx & 1023;
        int ks = rem >> 7;   int r = rem & 127;
        int lane = r >> 2,   q = r & 3;
        int gID = lane >> 2, tig = lane & 3;
        int co = gID + 8*(q & 1);
        int ci = ks*8 + tig + 4*(q >> 1);
        int dy = tap/3, dx = tap - dy*3;
        float v = (co < 10) ? offw[((co*64+ci)*3 + dy)*3 + dx] : 0.f;
        g_wCf[idx] = tf32cvt(v);
    }
    if (gtid >= 65536 && gtid < 65536+40)  g_ostats[gtid-65536] = 0.f;
    if (gtid >= 131072 && gtid < 131072+128) g_fstats[gtid-131072] = 0.f;

    for (int i = threadIdx.y; i < 32; i += 8)
        tile[i][threadIdx.x] = x[(size_t)(b*64 + c0 + i)*HWp + p0 + threadIdx.x];
    __syncthreads();
    for (int i = threadIdx.y; i < 32; i += 8)
        g_xT[(size_t)(b*HWp + p0 + i)*64 + c0 + threadIdx.x] = tile[threadIdx.x][i];
}

// ---------------- offset conv 3x3 64->10 via tf32 mma (implicit im2col) ----------------
#define CONVM_SMEM (390*68*4)
__global__ void __launch_bounds__(256) kConvM(const float* __restrict__ offb){
    extern __shared__ unsigned su[];
    unsigned* sV = su;            // [dy*130+jp][68]
    int h = blockIdx.x, b = blockIdx.y, t = threadIdx.x;
    int wid = t >> 5, lane = t & 31, gID = lane >> 2, tig = lane & 3;
    int n0 = wid*16;

    // incremental fill: r = dy*130+jp walks +16
    {
        int c4 = t & 15;
        int r = t >> 4;
        int jp = r, dy = 0;
        while (r < 390){
            int gh = h - 1 + dy, gw = jp - 1;
            float4 v = make_float4(0.f, 0.f, 0.f, 0.f);
            if (gh >= 0 && gh < 128 && gw >= 0 && gw < 128)
                v = *(const float4*)&g_xT[((size_t)b*HWp + gh*128 + gw)*64 + c4*4];
            uint4 tv;
            tv.x = tf32cvt(v.x); tv.y = tf32cvt(v.y);
            tv.z = tf32cvt(v.z); tv.w = tf32cvt(v.w);
            *(uint4*)&sV[r*68 + c4*4] = tv;
            r += 16; jp += 16;
            if (jp >= 130){ jp -= 130; dy++; }
        }
    }
    __syncthreads();

    float acc[2][4];
    #pragma unroll
    for (int nt = 0; nt < 2; nt++)
        #pragma unroll
        for (int p = 0; p < 4; p++) acc[nt][p] = 0.f;

    #pragma unroll
    for (int tap = 0; tap < 9; tap++){
        int dy = tap/3, dx = tap - dy*3;
        int vbase = dy*130 + dx;
        #pragma unroll
        for (int ks = 0; ks < 8; ks++){
            int kk = ks*8;
            uint4 f = *(const uint4*)&g_wCf[((tap*8 + ks) << 7) + (lane << 2)];
            #pragma unroll
            for (int nt = 0; nt < 2; nt++){
                int j = n0 + nt*8 + gID;
                unsigned b0 = sV[(vbase + j)*68 + kk + tig];
                unsigned b1 = sV[(vbase + j)*68 + kk + tig + 4];
                mma_tf32(acc[nt], f.x, f.y, f.z, f.w, b0, b1);
            }
        }
    }

    int co0 = gID, co1 = gID + 8;
    float bias0 = offb[co0];
    float bias1 = (gID < 2) ? offb[co1] : 0.f;
    float s0 = 0.f, ss0 = 0.f, s1 = 0.f, ss1 = 0.f;
    #pragma unroll
    for (int nt = 0; nt < 2; nt++){
        float c0 = acc[nt][0] + bias0, c1 = acc[nt][1] + bias0;
        int pix = h*128 + n0 + nt*8 + tig*2;
        *(float2*)&g_rawoff[((size_t)(b*10+co0))*HWp + pix] = make_float2(c0, c1);
        s0 += c0 + c1; ss0 += c0*c0 + c1*c1;
        if (gID < 2){
            float c2 = acc[nt][2] + bias1, c3 = acc[nt][3] + bias1;
            *(float2*)&g_rawoff[((size_t)(b*10+co1))*HWp + pix] = make_float2(c2, c3);
            s1 += c2 + c3; ss1 += c2*c2 + c3*c3;
        }
    }
    #pragma unroll
    for (int m = 1; m <= 4; m <<= 1){
        s0  += __shfl_xor_sync(0xffffffffu, s0,  m);
        ss0 += __shfl_xor_sync(0xffffffffu, ss0, m);
        s1  += __shfl_xor_sync(0xffffffffu, s1,  m);
        ss1 += __shfl_xor_sync(0xffffffffu, ss1, m);
    }
    if (tig == 0 && (gID & 1) == 0){
        int g0 = gID >> 1;
        atomicAdd(&g_ostats[(b*5 + g0)*2    ], s0);
        atomicAdd(&g_ostats[(b*5 + g0)*2 + 1], ss0);
        if (gID == 0){
            atomicAdd(&g_ostats[(b*5 + 4)*2    ], s1);
            atomicAdd(&g_ostats[(b*5 + 4)*2 + 1], ss1);
        }
    }
}

// ---------------- fused: GN+tanh+cumsum+ynew -> front-end GEMVs -> scan pass1 ----------------
__device__ __forceinline__ void comp_tv(int b, int l, const float* sMu, const float* sRs,
                                        const float* __restrict__ gnog,
                                        const float* __restrict__ gnob, float* tv){
    int tt = l & 1, r = l >> 1;
    int w = r & 127, r2 = r >> 7;
    int p = (r2*2 + tt)*128 + w;
    #pragma unroll
    for (int c = 0; c < 9; c++){
        float raw = g_rawoff[((size_t)(b*10+c))*HWp + p];
        float xn = (raw - sMu[c>>1]) * sRs[c>>1] * gnog[c] + gnob[c];
        tv[c] = ftanh(xn);
    }
}

#define FUS_SMEM (19339*4)
__global__ void __launch_bounds__(288) kFused(
        const float* __restrict__ gnog, const float* __restrict__ gnob,
        const float* __restrict__ ipw,  const float* __restrict__ cw,
        const float* __restrict__ cb,   const float* __restrict__ xpw,
        const float* __restrict__ dtw,  const float* __restrict__ dtb,
        const float* __restrict__ Alog){
    extern __shared__ float sm[];
    float* sXP  = sm;            // 259*19
    float* sIPW = sm + 4921;     // 324
    float* sXPW = sm + 5245;     // 594
    float* sCW  = sm + 5839;     // 72
    float* sCB  = sm + 5911;     // 18
    float* sDTW = sm + 5929;     // 18
    float* sDTB = sm + 5947;     // 18
    float* sMu  = sm + 5965;     // 5
    float* sRs  = sm + 5970;     // 5
    float* sDT  = sm + 5975;     // 18*257
    float* sXI  = sm + 10601;    // 18*257
    float* sB   = sm + 15227;    // 16*257
    int b = blockIdx.y, c = blockIdx.x, l0 = c*CH, t = threadIdx.x;

    for (int idx = t; idx < 324; idx += 288) sIPW[idx] = ipw[idx];
    for (int idx = t; idx < 594; idx += 288) sXPW[idx] = xpw[idx];
    if (t < 72) sCW[t] = cw[t];
    if (t < 18){ sCB[t] = cb[t]; sDTW[t] = dtw[t]; sDTB[t] = dtb[t]; }
    if (t < 5){
        float s  = g_ostats[(b*5+t)*2];
        float ss = g_ostats[(b*5+t)*2+1];
        float mu = s * (1.f/32768.f);
        float var = ss * (1.f/32768.f) - mu*mu;
        sMu[t] = mu;
        sRs[t] = rsqrtf(var + 1e-5f);
    }
    __syncthreads();

    if (t < CH){
        int l = l0 + t;
        float tv[9];
        comp_tv(b, l, sMu, sRs, gnog, gnob, tv);

        float cum[9];
        cum[4] = 0.f;
        cum[5] = tv[5]; cum[6] = cum[5]+tv[6]; cum[7] = cum[6]+tv[7]; cum[8] = cum[7]+tv[8];
        cum[3] = tv[3]; cum[2] = cum[3]+tv[2]; cum[1] = cum[2]+tv[1]; cum[0] = cum[1]+tv[0];

        int tt = l & 1, r = l >> 1;
        int w = r & 127, r2 = r >> 7;
        int h = r2*2 + tt, p = h*128 + w;
        #pragma unroll
        for (int k = 0; k < 9; k++)
            g_ynew[((size_t)(b*9+k))*HWp + p] = (float)h + cum[k];

        #pragma unroll
        for (int n = 0; n < 18; n++){
            float v = 0.f;
            #pragma unroll
            for (int m = 0; m < 9; m++) v += tv[m]*sIPW[n*9+m];
            sXP[(t+3)*19 + n] = v;
        }
        #pragma unroll
        for (int n = 0; n < 18; n++){
            float z = 0.f;
            #pragma unroll
            for (int m = 0; m < 9; m++) z += tv[m]*sIPW[(18+n)*9+m];
            g_gate[((size_t)(b*18+n))*LSEQ + l] = siluf(z);
        }
    } else if (t < CH+3){
        int bi = t - CH;
        int l2 = l0 - 3 + bi;
        if (l2 >= 0){
            float tv2[9];
            comp_tv(b, l2, sMu, sRs, gnog, gnob, tv2);
            #pragma unroll
            for (int n = 0; n < 18; n++){
                float v = 0.f;
                #pragma unroll
                for (int m = 0; m < 9; m++) v += tv2[m]*sIPW[n*9+m];
                sXP[bi*19 + n] = v;
            }
        } else {
            #pragma unroll
            for (int n = 0; n < 18; n++) sXP[bi*19 + n] = 0.f;
        }
    }
    __syncthreads();

    if (t < CH){
        int l = l0 + t;
        float xi[18];
        #pragma unroll
        for (int d = 0; d < 18; d++){
            float xc = sCB[d];
            #pragma unroll
            for (int j = 0; j < 4; j++) xc += sCW[d*4+j]*sXP[(t+j)*19 + d];
            xi[d] = siluf(xc);
        }
        float dtr = 0.f;
        #pragma unroll
        for (int d = 0; d < 18; d++) dtr += xi[d]*sXPW[d];
        #pragma unroll
        for (int s = 0; s < 16; s++){
            float bv = 0.f, cv = 0.f;
            #pragma unroll
            for (int d = 0; d < 18; d++){
                bv += xi[d]*sXPW[(1+s)*18 + d];
                cv += xi[d]*sXPW[(17+s)*18 + d];
            }
            sB[s*257 + t] = bv;
            g_Bsc[((size_t)(b*16+s))*LSEQ + l] = bv;
            g_Csc[((size_t)(b*16+s))*LSEQ + l] = cv;
        }
        #pragma unroll
        for (int d = 0; d < 18; d++){
            float a = dtr*sDTW[d] + sDTB[d];
            float dtv = softplusf(a);
            sDT[d*257 + t] = dtv;
            sXI[d*257 + t] = xi[d];
            g_dt[((size_t)(b*18+d))*LSEQ + l] = dtv;
            g_xi[((size_t)(b*18+d))*LSEQ + l] = xi[d];
        }
    }
    __syncthreads();

    int d = t / 16, s = t % 16;
    float a = -expf(Alog[d*16+s]);
    float p = 1.f, q = 0.f;
    for (int i = 0; i < CH; i++){
        float dt = sDT[d*257+i];
        float da = __expf(dt*a);
        q = da*q + dt*sB[s*257+i]*sXI[d*257+i];
        p *= da;
    }
    g_P[(b*NCH+c)*288 + t] = p;
    g_Q[(b*NCH+c)*288 + t] = q;
}

// ---------------- scan pass2: serial carry, t-sliced 18/block ----------------
#define SCAN2_SMEM (2*NCH*18*4)
__global__ void __launch_bounds__(288) kScan2(){
    extern __shared__ float sm[];
    float* sP = sm;            // [c][18]
    float* sQ = sm + NCH*18;
    int b = blockIdx.x, sl = blockIdx.y, t = threadIdx.x;
    int t0 = sl*18;
    for (int idx = t; idx < NCH*18; idx += 288){
        int c = idx/18, tt = idx - c*18;
        sP[idx] = g_P[(b*NCH+c)*288 + t0 + tt];
        sQ[idx] = g_Q[(b*NCH+c)*288 + t0 + tt];
    }
    __syncthreads();
    if (t < 18){
        float h = 0.f;
        #pragma unroll 8
        for (int c = 0; c < NCH; c++){
            g_hinit[(b*NCH+c)*288 + t0 + t] = h;
            h = sP[c*18+t]*h + sQ[c*18+t];
        }
    }
}

// ---------------- scan pass3: replay + output + py ----------------
// strides 260 (16B-aligned rows) -> float4 refill
#define S3S 260
#define SCAN3_SMEM ((70*S3S + 18*257 + 162 + 18)*4)
__global__ void __launch_bounds__(288) kScan3(const float* __restrict__ Alog, const float* __restrict__ Dp,
                       const float* __restrict__ opw,  const float* __restrict__ altho){
    extern __shared__ float sm[];
    float* sDT = sm;                 // 18*260
    float* sXI = sm + 18*S3S;        // 18*260
    float* sB  = sm + 36*S3S;        // 16*260
    float* sC  = sm + 52*S3S;        // 16*260
    float* sYS = sm + 68*S3S + 2*S3S - 2*S3S;  // placed after sC
    float* base2 = sm + 68*S3S;
    sYS = base2;                     // 18*257
    float* sOPW = base2 + 18*257;    // 162
    float* sDP  = sOPW + 162;        // 18
    int b = blockIdx.y, c = blockIdx.x, l0 = c*CH, t = threadIdx.x;

    for (int idx = t; idx < 18*(CH/4); idx += 288){
        int dd = idx >> 6;           // CH/4 = 64
        int i4 = (idx & 63) << 2;
        *(float4*)&sDT[dd*S3S + i4] = *(const float4*)&g_dt[((size_t)(b*18+dd))*LSEQ + l0 + i4];
        *(float4*)&sXI[dd*S3S + i4] = *(const float4*)&g_xi[((size_t)(b*18+dd))*LSEQ + l0 + i4];
    }
    for (int idx = t; idx < 16*(CH/4); idx += 288){
        int ss = idx >> 6;
        int i4 = (idx & 63) << 2;
        *(float4*)&sB[ss*S3S + i4] = *(const float4*)&g_Bsc[((size_t)(b*16+ss))*LSEQ + l0 + i4];
        *(float4*)&sC[ss*S3S + i4] = *(const float4*)&g_Csc[((size_t)(b*16+ss))*LSEQ + l0 + i4];
    }
    if (t < 162) sOPW[t] = opw[t];
    if (t < 18)  sDP[t]  = Dp[t];
    __syncthreads();

    {
        int d = t / 16, s = t % 16;
        float a = -expf(Alog[d*16+s]);
        float h = g_hinit[(b*NCH+c)*288 + t];
        for (int i = 0; i < CH; i++){
            float dt = sDT[d*S3S+i];
            float da = __expf(dt*a);
            h = da*h + dt*sB[s*S3S+i]*sXI[d*S3S+i];
            float v = h * sC[s*S3S+i];
            v += __shfl_xor_sync(0xffffffffu, v, 1);
            v += __shfl_xor_sync(0xffffffffu, v, 2);
            v += __shfl_xor_sync(0xffffffffu, v, 4);
            v += __shfl_xor_sync(0xffffffffu, v, 8);
            if ((t & 15) == 0) sYS[d*257+i] = v;
        }
    }
    __syncthreads();

    if (t < CH){
        int l = l0 + t;
        float wgt = fmaxf(softplusf(altho[0]), 0.01f);
        float ym[9];
        #pragma unroll
        for (int m = 0; m < 9; m++) ym[m] = 0.f;
        #pragma unroll
        for (int dd = 0; dd < 18; dd++){
            float yv = (sYS[dd*257+t] + sDP[dd]*sXI[dd*S3S+t]) * g_gate[((size_t)(b*18+dd))*LSEQ + l];
            #pragma unroll
            for (int m = 0; m < 9; m++) ym[m] += yv * sOPW[m*18+dd];
        }
        int tt = l & 1, r = l >> 1;
        int w = r & 127, h2 = r >> 7;
        int pix = (h2*2 + tt)*128 + w;
        #pragma unroll
        for (int m = 0; m < 9; m++){
            float py = wgt*ym[m] + g_ynew[((size_t)(b*9+m))*HWp + pix];
            py = fminf(fmaxf(py, 0.f), 127.f);
            g_py[((size_t)(b*9+m))*HWp + pix] = py;
        }
    }
}

// ---------------- deformable gather + tf32 tensor-core contraction + GN stats ----------------
#define DEF_SMEM (128*68*4)
__global__ void __launch_bounds__(256) kDeform(const float* __restrict__ dscb){
    extern __shared__ unsigned sV[];    // [pix][ci] stride 68
    int i = blockIdx.x, b = blockIdx.y, t = threadIdx.x;
    int wid = t >> 5, lane = t & 31;
    int gID = lane >> 2, tig = lane & 3;
    int ctq = wid & 3, ct = ctq*16;
    int pt = (wid >> 2)*64;

    float acc[8][4];
    #pragma unroll
    for (int nt = 0; nt < 8; nt++)
        #pragma unroll
        for (int p = 0; p < 4; p++) acc[nt][p] = 0.f;

    for (int k = 0; k < 9; k++){
        int p0 = wid*16;
        #pragma unroll
        for (int pp = 0; pp < 16; pp++){
            int j = p0 + pp;
            float pyv = g_py[((size_t)(b*9+k))*HWp + i*128 + j];
            float fy0 = floorf(pyv);
            int y0 = (int)fy0;
            float wy = pyv - fy0;
            float wy0 = 1.f - wy;
            int y1 = min(y0 + 1, 127);
            int xc = min(max(j + k - 4, 0), 127);
            const float* base0 = &g_xT[((size_t)b*HWp + y0*128 + xc)*64];
            const float* base1 = &g_xT[((size_t)b*HWp + y1*128 + xc)*64];
            float vL = base0[lane]*wy0    + base1[lane]*wy;
            float vH = base0[lane+32]*wy0 + base1[lane+32]*wy;
            sV[j*68 + lane]      = tf32cvt(vL);
            sV[j*68 + lane + 32] = tf32cvt(vH);
        }
        __syncthreads();

        #pragma unroll
        for (int ks = 0; ks < 8; ks++){
            int kk = ks*8;
            uint4 f = *(const uint4*)&g_wAf[((((k*4 + ctq)*8) + ks) << 7) + (lane << 2)];
            #pragma unroll
            for (int nt = 0; nt < 8; nt++){
                int n0 = pt + nt*8;
                unsigned b0 = sV[(n0+gID)*68 + kk + tig];
                unsigned b1 = sV[(n0+gID)*68 + kk + tig + 4];
                mma_tf32(acc[nt], f.x, f.y, f.z, f.w, b0, b1);
            }
        }
        __syncthreads();
    }

    int co0 = ct + gID, co1 = ct + gID + 8;
    float bias0 = dscb[co0], bias1 = dscb[co1];
    float s0 = 0.f, ss0 = 0.f, s1 = 0.f, ss1 = 0.f;
    #pragma unroll
    for (int nt = 0; nt < 8; nt++){
        float c0 = acc[nt][0] + bias0, c1 = acc[nt][1] + bias0;
        float c2 = acc[nt][2] + bias1, c3 = acc[nt][3] + bias1;
        size_t pix = (size_t)i*128 + pt + nt*8 + tig*2;
        *(float2*)&g_outraw[((size_t)(b*64+co0))*HWp + pix] = make_float2(c0, c1);
        *(float2*)&g_outraw[((size_t)(b*64+co1))*HWp + pix] = make_float2(c2, c3);
        s0 += c0 + c1; ss0 += c0*c0 + c1*c1;
        s1 += c2 + c3; ss1 += c2*c2 + c3*c3;
    }
    #pragma unroll
    for (int m = 1; m <= 8; m <<= 1){
        s0  += __shfl_xor_sync(0xffffffffu, s0,  m);
        ss0 += __shfl_xor_sync(0xffffffffu, ss0, m);
        s1  += __shfl_xor_sync(0xffffffffu, s1,  m);
        ss1 += __shfl_xor_sync(0xffffffffu, ss1, m);
    }
    if ((lane & 15) == 0){
        int g0 = (ct >> 2) + (lane >> 4);
        atomicAdd(&g_fstats[(b*16 + g0)*2    ], s0);
        atomicAdd(&g_fstats[(b*16 + g0)*2 + 1], ss0);
        atomicAdd(&g_fstats[(b*16 + g0 + 2)*2    ], s1);
        atomicAdd(&g_fstats[(b*16 + g0 + 2)*2 + 1], ss1);
    }
}

// ---------------- final GN (float4) ----------------
__global__ void kFinalGN(const float* __restrict__ gng, const float* __restrict__ gnb,
                         float* __restrict__ out){
    int idx4 = blockIdx.x*256 + threadIdx.x;
    int idx = idx4*4;
    int b = idx >> 20;
    int c = (idx >> 14) & 63;
    int g = c >> 2;
    float s  = g_fstats[(b*16+g)*2];
    float ss = g_fstats[(b*16+g)*2+1];
    float mu = s * (1.f/65536.f);
    float var = ss * (1.f/65536.f) - mu*mu;
    float rs = rsqrtf(var + 1e-5f) * gng[c];
    float bb = gnb[c];
    float4 v = *(const float4*)&g_outraw[idx];
    float4 o;
    o.x = (v.x - mu)*rs + bb;
    o.y = (v.y - mu)*rs + bb;
    o.z = (v.z - mu)*rs + bb;
    o.w = (v.w - mu)*rs + bb;
    *(float4*)&out[idx] = o;
}

extern "C" void kernel_launch(void* const* d_in, const int* in_sizes, int n_in,
                              void* d_out, int out_size){
    const float* x     = (const float*)d_in[0];
    const float* offw  = (const float*)d_in[1];
    const float* offb  = (const float*)d_in[2];
    const float* gnog  = (const float*)d_in[3];
    const float* gnob  = (const float*)d_in[4];
    const float* altho = (const float*)d_in[5];
    const float* ipw   = (const float*)d_in[6];
    const float* cw    = (const float*)d_in[7];
    const float* cb    = (const float*)d_in[8];
    const float* xpw   = (const float*)d_in[9];
    const float* dtw   = (const float*)d_in[10];
    const float* dtb   = (const float*)d_in[11];
    const float* Alog  = (const float*)d_in[12];
    const float* Dp    = (const float*)d_in[13];
    const float* opw   = (const float*)d_in[14];
    const float* dscw  = (const float*)d_in[15];
    const float* dscb  = (const float*)d_in[16];
    const float* gng   = (const float*)d_in[17];
    const float* gnb   = (const float*)d_in[18];
    float* out = (float*)d_out;

    cudaFuncSetAttribute(kConvM,  cudaFuncAttributeMaxDynamicSharedMemorySize, CONVM_SMEM);
    cudaFuncSetAttribute(kFused,  cudaFuncAttributeMaxDynamicSharedMemorySize, FUS_SMEM);
    cudaFuncSetAttribute(kScan3,  cudaFuncAttributeMaxDynamicSharedMemorySize, SCAN3_SMEM);
    cudaFuncSetAttribute(kDeform, cudaFuncAttributeMaxDynamicSharedMemorySize, DEF_SMEM);

    kPrep<<<dim3(512, 2, 4), dim3(32, 8)>>>(x, dscw, offw);
    kConvM<<<dim3(128, 4), 256, CONVM_SMEM>>>(offb);
    kFused<<<dim3(NCH, 4), 288, FUS_SMEM>>>(gnog, gnob, ipw, cw, cb, xpw, dtw, dtb, Alog);
    kScan2<<<dim3(4, 16), 288, SCAN2_SMEM>>>();
    kScan3<<<dim3(NCH, 4), 288, SCAN3_SMEM>>>(Alog, Dp, opw, altho);
    kDeform<<<dim3(128, 4), 256, DEF_SMEM>>>(dscb);
    kFinalGN<<<4096, 256>>>(gng, gnb, out);
}

// round 15
// speedup vs baseline: 1.2977x; 1.0702x over previous
#include <cuda_runtime.h>
#include <math.h>

#define Bn   4
#define HWp  16384
#define LSEQ 16384
#define CH   256
#define NCH  64

// ---------------- tf32 mma helpers ----------------
__device__ __forceinline__ unsigned tf32cvt(float v){
    unsigned r; asm("cvt.rna.tf32.f32 %0, %1;" : "=r"(r) : "f"(v)); return r;
}
__device__ __forceinline__ void mma_tf32(float* d, unsigned a0, unsigned a1, unsigned a2, unsigned a3,
                                         unsigned b0, unsigned b1){
    asm("mma.sync.aligned.m16n8k8.row.col.f32.tf32.tf32.f32 "
        "{%0,%1,%2,%3}, {%4,%5,%6,%7}, {%8,%9}, {%0,%1,%2,%3};"
        : "+f"(d[0]), "+f"(d[1]), "+f"(d[2]), "+f"(d[3])
        : "r"(a0), "r"(a1), "r"(a2), "r"(a3), "r"(b0), "r"(b1));
}

// ---------------- scratch ----------------
__device__ float g_xT[Bn*HWp*64];        // [b][pix][c]
__device__ float g_rawoff[Bn*10*HWp];    // offset conv out, [b][co][pix]
__device__ float g_ostats[Bn*5*2];
__device__ float g_ynew[Bn*9*HWp];       // [b][k][pix]
__device__ float g_P[Bn*NCH*288];
__device__ float g_Q[Bn*NCH*288];
__device__ float g_py[Bn*9*HWp];         // [b][k][pix]
__device__ unsigned g_wAf[9*64*64];      // deform conv A, mma fragment order
__device__ unsigned g_wCf[9*8*128];      // offset conv A, mma fragment order
__device__ float g_outraw[Bn*64*HWp];
__device__ float g_fstats[Bn*16*2];
__device__ unsigned g_cnt;               // grid-barrier counter (zeroed by kPrep)

__device__ __forceinline__ float softplusf(float x){
    return x > 20.f ? x : log1pf(__expf(x));
}
__device__ __forceinline__ float siluf(float x){
    return __fdividef(x, 1.f + __expf(-x));
}
__device__ __forceinline__ float ftanh(float x){
    float xc = fminf(fmaxf(x, -15.f), 15.f);
    float e = __expf(2.f*xc);
    return __fdividef(e - 1.f, e + 1.f);
}

// ---------------- prep: transpose x + zero stats/counter + weight tf32 conversions ----------------
__global__ void kPrep(const float* __restrict__ x, const float* __restrict__ dscw,
                      const float* __restrict__ offw){
    __shared__ float tile[32][33];
    int b = blockIdx.z, c0 = blockIdx.y*32, p0 = blockIdx.x*32;
    int bid = (blockIdx.z*gridDim.y + blockIdx.y)*gridDim.x + blockIdx.x;
    int gtid = bid*256 + threadIdx.y*32 + threadIdx.x;

    if (gtid == 0) g_cnt = 0u;
    if (gtid < 36864){
        int k = gtid >> 12;
        int rem = gtid & 4095;
        int ctq = rem >> 10;
        int rem2 = rem & 1023;
        int ks = rem2 >> 7;
        int r = rem2 & 127;
        int lane = r >> 2, q = r & 3;
        int gID = lane >> 2, tig = lane & 3;
        int co = ctq*16 + gID + ((q & 1) << 3);
        int ci = ks*8 + tig + ((q >> 1) << 2);
        g_wAf[gtid] = tf32cvt(dscw[(co*64 + ci)*9 + k]);
    }
    if (gtid >= 40960 && gtid < 40960+9216){
        int idx = gtid - 40960;
        int tap = idx >> 10; int rem = idx & 1023;
        int ks = rem >> 7;   int r = rem & 127;
        int lane = r >> 2,   q = r & 3;
        int gID = lane >> 2, tig = lane & 3;
        int co = gID + 8*(q & 1);
        int ci = ks*8 + tig + 4*(q >> 1);
        int dy = tap/3, dx = tap - dy*3;
        float v = (co < 10) ? offw[((co*64+ci)*3 + dy)*3 + dx] : 0.f;
        g_wCf[idx] = tf32cvt(v);
    }
    if (gtid >= 65536 && gtid < 65536+40)  g_ostats[gtid-65536] = 0.f;
    if (gtid >= 131072 && gtid < 131072+128) g_fstats[gtid-131072] = 0.f;

    for (int i = threadIdx.y; i < 32; i += 8)
        tile[i][threadIdx.x] = x[(size_t)(b*64 + c0 + i)*HWp + p0 + threadIdx.x];
    __syncthreads();
    for (int i = threadIdx.y; i < 32; i += 8)
        g_xT[(size_t)(b*HWp + p0 + i)*64 + c0 + threadIdx.x] = tile[threadIdx.x][i];
}

// ---------------- offset conv 3x3 64->10 via tf32 mma (implicit im2col) ----------------
#define CONVM_SMEM (390*68*4)
__global__ void __launch_bounds__(256) kConvM(const float* __restrict__ offb){
    extern __shared__ unsigned su[];
    unsigned* sV = su;            // [dy*130+jp][68]
    int h = blockIdx.x, b = blockIdx.y, t = threadIdx.x;
    int wid = t >> 5, lane = t & 31, gID = lane >> 2, tig = lane & 3;
    int n0 = wid*16;

    {
        int c4 = t & 15;
        int r = t >> 4;
        int jp = r, dy = 0;
        while (r < 390){
            int gh = h - 1 + dy, gw = jp - 1;
            float4 v = make_float4(0.f, 0.f, 0.f, 0.f);
            if (gh >= 0 && gh < 128 && gw >= 0 && gw < 128)
                v = *(const float4*)&g_xT[((size_t)b*HWp + gh*128 + gw)*64 + c4*4];
            uint4 tv;
            tv.x = tf32cvt(v.x); tv.y = tf32cvt(v.y);
            tv.z = tf32cvt(v.z); tv.w = tf32cvt(v.w);
            *(uint4*)&sV[r*68 + c4*4] = tv;
            r += 16; jp += 16;
            if (jp >= 130){ jp -= 130; dy++; }
        }
    }
    __syncthreads();

    float acc[2][4];
    #pragma unroll
    for (int nt = 0; nt < 2; nt++)
        #pragma unroll
        for (int p = 0; p < 4; p++) acc[nt][p] = 0.f;

    #pragma unroll
    for (int tap = 0; tap < 9; tap++){
        int dy = tap/3, dx = tap - dy*3;
        int vbase = dy*130 + dx;
        #pragma unroll
        for (int ks = 0; ks < 8; ks++){
            int kk = ks*8;
            uint4 f = *(const uint4*)&g_wCf[((tap*8 + ks) << 7) + (lane << 2)];
            #pragma unroll
            for (int nt = 0; nt < 2; nt++){
                int j = n0 + nt*8 + gID;
                unsigned b0 = sV[(vbase + j)*68 + kk + tig];
                unsigned b1 = sV[(vbase + j)*68 + kk + tig + 4];
                mma_tf32(acc[nt], f.x, f.y, f.z, f.w, b0, b1);
            }
        }
    }

    int co0 = gID, co1 = gID + 8;
    float bias0 = offb[co0];
    float bias1 = (gID < 2) ? offb[co1] : 0.f;
    float s0 = 0.f, ss0 = 0.f, s1 = 0.f, ss1 = 0.f;
    #pragma unroll
    for (int nt = 0; nt < 2; nt++){
        float c0 = acc[nt][0] + bias0, c1 = acc[nt][1] + bias0;
        int pix = h*128 + n0 + nt*8 + tig*2;
        *(float2*)&g_rawoff[((size_t)(b*10+co0))*HWp + pix] = make_float2(c0, c1);
        s0 += c0 + c1; ss0 += c0*c0 + c1*c1;
        if (gID < 2){
            float c2 = acc[nt][2] + bias1, c3 = acc[nt][3] + bias1;
            *(float2*)&g_rawoff[((size_t)(b*10+co1))*HWp + pix] = make_float2(c2, c3);
            s1 += c2 + c3; ss1 += c2*c2 + c3*c3;
        }
    }
    #pragma unroll
    for (int m = 1; m <= 4; m <<= 1){
        s0  += __shfl_xor_sync(0xffffffffu, s0,  m);
        ss0 += __shfl_xor_sync(0xffffffffu, ss0, m);
        s1  += __shfl_xor_sync(0xffffffffu, s1,  m);
        ss1 += __shfl_xor_sync(0xffffffffu, ss1, m);
    }
    if (tig == 0 && (gID & 1) == 0){
        int g0 = gID >> 1;
        atomicAdd(&g_ostats[(b*5 + g0)*2    ], s0);
        atomicAdd(&g_ostats[(b*5 + g0)*2 + 1], ss0);
        if (gID == 0){
            atomicAdd(&g_ostats[(b*5 + 4)*2    ], s1);
            atomicAdd(&g_ostats[(b*5 + 4)*2 + 1], ss1);
        }
    }
}

// ---------------- merged mamba: front-end -> pass1 -> grid barrier -> lookback -> replay -> py ----------------
// 256 blocks, 110.4 KB smem, 2 blocks/SM forced -> all blocks co-resident (spin barrier safe).
__device__ __forceinline__ void comp_tv(int b, int l, const float* sMu, const float* sRs,
                                        const float* __restrict__ gnog,
                                        const float* __restrict__ gnob, float* tv){
    int tt = l & 1, r = l >> 1;
    int w = r & 127, r2 = r >> 7;
    int p = (r2*2 + tt)*128 + w;
    #pragma unroll
    for (int c = 0; c < 9; c++){
        float raw = g_rawoff[((size_t)(b*10+c))*HWp + p];
        float xn = (raw - sMu[c>>1]) * sRs[c>>1] * gnog[c] + gnob[c];
        tv[c] = ftanh(xn);
    }
}

#define MAMBA_SMEM (28257*4)
__global__ void __launch_bounds__(288, 2) kMamba(
        const float* __restrict__ gnog, const float* __restrict__ gnob,
        const float* __restrict__ ipw,  const float* __restrict__ cw,
        const float* __restrict__ cb,   const float* __restrict__ xpw,
        const float* __restrict__ dtw,  const float* __restrict__ dtb,
        const float* __restrict__ Alog, const float* __restrict__ Dp,
        const float* __restrict__ opw,  const float* __restrict__ altho){
    extern __shared__ float sm[];
    float* sXP   = sm;             // 4921 (phase A); overlaid by sYS in phase D
    float* sYS   = sm;             // 18*257 = 4626
    float* sIPW  = sm + 4921;      // 324
    float* sXPW  = sm + 5245;      // 594
    float* sCW   = sm + 5839;      // 72
    float* sCB   = sm + 5911;      // 18
    float* sDTW  = sm + 5929;      // 18
    float* sDTB  = sm + 5947;      // 18
    float* sMu   = sm + 5965;      // 5
    float* sRs   = sm + 5970;      // 5
    float* sDT   = sm + 5975;      // 18*257
    float* sXI   = sm + 10601;     // 18*257
    float* sB    = sm + 15227;     // 16*257
    float* sC    = sm + 19339;     // 16*257
    float* sGate = sm + 23451;     // 18*257
    float* sOPW  = sm + 28077;     // 162
    float* sDP   = sm + 28239;     // 18
    int b = blockIdx.y, c = blockIdx.x, l0 = c*CH, t = threadIdx.x;

    for (int idx = t; idx < 324; idx += 288) sIPW[idx] = ipw[idx];
    for (int idx = t; idx < 594; idx += 288) sXPW[idx] = xpw[idx];
    if (t < 72) sCW[t] = cw[t];
    if (t < 18){ sCB[t] = cb[t]; sDTW[t] = dtw[t]; sDTB[t] = dtb[t]; }
    if (t >= 32 && t < 194) sOPW[t-32] = opw[t-32];
    if (t >= 224 && t < 242) sDP[t-224] = Dp[t-224];
    if (t < 5){
        float s  = g_ostats[(b*5+t)*2];
        float ss = g_ostats[(b*5+t)*2+1];
        float mu = s * (1.f/32768.f);
        float var = ss * (1.f/32768.f) - mu*mu;
        sMu[t] = mu;
        sRs[t] = rsqrtf(var + 1e-5f);
    }
    __syncthreads();

    // ---- phase A: front-end ----
    if (t < CH){
        int l = l0 + t;
        float tv[9];
        comp_tv(b, l, sMu, sRs, gnog, gnob, tv);

        float cum[9];
        cum[4] = 0.f;
        cum[5] = tv[5]; cum[6] = cum[5]+tv[6]; cum[7] = cum[6]+tv[7]; cum[8] = cum[7]+tv[8];
        cum[3] = tv[3]; cum[2] = cum[3]+tv[2]; cum[1] = cum[2]+tv[1]; cum[0] = cum[1]+tv[0];

        int tt = l & 1, r = l >> 1;
        int w = r & 127, r2 = r >> 7;
        int h = r2*2 + tt, p = h*128 + w;
        #pragma unroll
        for (int k = 0; k < 9; k++)
            g_ynew[((size_t)(b*9+k))*HWp + p] = (float)h + cum[k];

        #pragma unroll
        for (int n = 0; n < 18; n++){
            float v = 0.f;
            #pragma unroll
            for (int m = 0; m < 9; m++) v += tv[m]*sIPW[n*9+m];
            sXP[(t+3)*19 + n] = v;
        }
        #pragma unroll
        for (int n = 0; n < 18; n++){
            float z = 0.f;
            #pragma unroll
            for (int m = 0; m < 9; m++) z += tv[m]*sIPW[(18+n)*9+m];
            sGate[n*257 + t] = siluf(z);
        }
    } else if (t < CH+3){
        int bi = t - CH;
        int l2 = l0 - 3 + bi;
        if (l2 >= 0){
            float tv2[9];
            comp_tv(b, l2, sMu, sRs, gnog, gnob, tv2);
            #pragma unroll
            for (int n = 0; n < 18; n++){
                float v = 0.f;
                #pragma unroll
                for (int m = 0; m < 9; m++) v += tv2[m]*sIPW[n*9+m];
                sXP[bi*19 + n] = v;
            }
        } else {
            #pragma unroll
            for (int n = 0; n < 18; n++) sXP[bi*19 + n] = 0.f;
        }
    }
    __syncthreads();

    if (t < CH){
        float xi[18];
        #pragma unroll
        for (int d = 0; d < 18; d++){
            float xc = sCB[d];
            #pragma unroll
            for (int j = 0; j < 4; j++) xc += sCW[d*4+j]*sXP[(t+j)*19 + d];
            xi[d] = siluf(xc);
        }
        float dtr = 0.f;
        #pragma unroll
        for (int d = 0; d < 18; d++) dtr += xi[d]*sXPW[d];
        #pragma unroll
        for (int s = 0; s < 16; s++){
            float bv = 0.f, cv = 0.f;
            #pragma unroll
            for (int d = 0; d < 18; d++){
                bv += xi[d]*sXPW[(1+s)*18 + d];
                cv += xi[d]*sXPW[(17+s)*18 + d];
            }
            sB[s*257 + t] = bv;
            sC[s*257 + t] = cv;
        }
        #pragma unroll
        for (int d = 0; d < 18; d++){
            float a = dtr*sDTW[d] + sDTB[d];
            sDT[d*257 + t] = softplusf(a);
            sXI[d*257 + t] = xi[d];
        }
    }
    __syncthreads();

    // ---- phase B: pass-1 scan + publish (P,Q) ----
    int d = t / 16, s = t % 16;
    float a = -expf(Alog[d*16+s]);
    {
        float p = 1.f, q = 0.f;
        for (int i = 0; i < CH; i++){
            float dt = sDT[d*257+i];
            float da = __expf(dt*a);
            q = da*q + dt*sB[s*257+i]*sXI[d*257+i];
            p *= da;
        }
        g_P[(b*NCH+c)*288 + t] = p;
        g_Q[(b*NCH+c)*288 + t] = q;
    }
    __syncthreads();
    __threadfence();
    if (t == 0) atomicAdd(&g_cnt, 1u);

    // ---- grid barrier: spin until all 256 blocks published ----
    if (t == 0){
        while (*((volatile unsigned*)&g_cnt) < (unsigned)(NCH*Bn)) __nanosleep(64);
    }
    __syncthreads();
    __threadfence();

    // ---- phase C: lookback — combine predecessor aggregates ----
    float h = 0.f;
    for (int cc = 0; cc < c; cc++){
        float pp = __ldcg(&g_P[(b*NCH+cc)*288 + t]);
        float qq = __ldcg(&g_Q[(b*NCH+cc)*288 + t]);
        h = pp*h + qq;
    }

    // ---- phase D: replay + epilogue ----
    for (int i = 0; i < CH; i++){
        float dt = sDT[d*257+i];
        float da = __expf(dt*a);
        h = da*h + dt*sB[s*257+i]*sXI[d*257+i];
        float v = h * sC[s*257+i];
        v += __shfl_xor_sync(0xffffffffu, v, 1);
        v += __shfl_xor_sync(0xffffffffu, v, 2);
        v += __shfl_xor_sync(0xffffffffu, v, 4);
        v += __shfl_xor_sync(0xffffffffu, v, 8);
        if ((t & 15) == 0) sYS[d*257+i] = v;
    }
    __syncthreads();

    if (t < CH){
        int l = l0 + t;
        float wgt = fmaxf(softplusf(altho[0]), 0.01f);
        float ym[9];
        #pragma unroll
        for (int m = 0; m < 9; m++) ym[m] = 0.f;
        #pragma unroll
        for (int dd = 0; dd < 18; dd++){
            float yv = (sYS[dd*257+t] + sDP[dd]*sXI[dd*257+t]) * sGate[dd*257+t];
            #pragma unroll
            for (int m = 0; m < 9; m++) ym[m] += yv * sOPW[m*18+dd];
        }
        int tt = l & 1, r = l >> 1;
        int w = r & 127, h2 = r >> 7;
        int pix = (h2*2 + tt)*128 + w;
        #pragma unroll
        for (int m = 0; m < 9; m++){
            float py = wgt*ym[m] + g_ynew[((size_t)(b*9+m))*HWp + pix];
            py = fminf(fmaxf(py, 0.f), 127.f);
            g_py[((size_t)(b*9+m))*HWp + pix] = py;
        }
    }
}

// ---------------- deformable gather + tf32 tensor-core contraction + GN stats ----------------
#define DEF_SMEM (128*68*4)
__global__ void __launch_bounds__(256) kDeform(const float* __restrict__ dscb){
    extern __shared__ unsigned sV[];    // [pix][ci] stride 68
    int i = blockIdx.x, b = blockIdx.y, t = threadIdx.x;
    int wid = t >> 5, lane = t & 31;
    int gID = lane >> 2, tig = lane & 3;
    int ctq = wid & 3, ct = ctq*16;
    int pt = (wid >> 2)*64;

    float acc[8][4];
    #pragma unroll
    for (int nt = 0; nt < 8; nt++)
        #pragma unroll
        for (int p = 0; p < 4; p++) acc[nt][p] = 0.f;

    for (int k = 0; k < 9; k++){
        int p0 = wid*16;
        #pragma unroll
        for (int pp = 0; pp < 16; pp++){
            int j = p0 + pp;
            float pyv = g_py[((size_t)(b*9+k))*HWp + i*128 + j];
            float fy0 = floorf(pyv);
            int y0 = (int)fy0;
            float wy = pyv - fy0;
            float wy0 = 1.f - wy;
            int y1 = min(y0 + 1, 127);
            int xc = min(max(j + k - 4, 0), 127);
            const float* base0 = &g_xT[((size_t)b*HWp + y0*128 + xc)*64];
            const float* base1 = &g_xT[((size_t)b*HWp + y1*128 + xc)*64];
            float vL = base0[lane]*wy0    + base1[lane]*wy;
            float vH = base0[lane+32]*wy0 + base1[lane+32]*wy;
            sV[j*68 + lane]      = tf32cvt(vL);
            sV[j*68 + lane + 32] = tf32cvt(vH);
        }
        __syncthreads();

        #pragma unroll
        for (int ks = 0; ks < 8; ks++){
            int kk = ks*8;
            uint4 f = *(const uint4*)&g_wAf[((((k*4 + ctq)*8) + ks) << 7) + (lane << 2)];
            #pragma unroll
            for (int nt = 0; nt < 8; nt++){
                int n0 = pt + nt*8;
                unsigned b0 = sV[(n0+gID)*68 + kk + tig];
                unsigned b1 = sV[(n0+gID)*68 + kk + tig + 4];
                mma_tf32(acc[nt], f.x, f.y, f.z, f.w, b0, b1);
            }
        }
        __syncthreads();
    }

    int co0 = ct + gID, co1 = ct + gID + 8;
    float bias0 = dscb[co0], bias1 = dscb[co1];
    float s0 = 0.f, ss0 = 0.f, s1 = 0.f, ss1 = 0.f;
    #pragma unroll
    for (int nt = 0; nt < 8; nt++){
        float c0 = acc[nt][0] + bias0, c1 = acc[nt][1] + bias0;
        float c2 = acc[nt][2] + bias1, c3 = acc[nt][3] + bias1;
        size_t pix = (size_t)i*128 + pt + nt*8 + tig*2;
        *(float2*)&g_outraw[((size_t)(b*64+co0))*HWp + pix] = make_float2(c0, c1);
        *(float2*)&g_outraw[((size_t)(b*64+co1))*HWp + pix] = make_float2(c2, c3);
        s0 += c0 + c1; ss0 += c0*c0 + c1*c1;
        s1 += c2 + c3; ss1 += c2*c2 + c3*c3;
    }
    #pragma unroll
    for (int m = 1; m <= 8; m <<= 1){
        s0  += __shfl_xor_sync(0xffffffffu, s0,  m);
        ss0 += __shfl_xor_sync(0xffffffffu, ss0, m);
        s1  += __shfl_xor_sync(0xffffffffu, s1,  m);
        ss1 += __shfl_xor_sync(0xffffffffu, ss1, m);
    }
    if ((lane & 15) == 0){
        int g0 = (ct >> 2) + (lane >> 4);
        atomicAdd(&g_fstats[(b*16 + g0)*2    ], s0);
        atomicAdd(&g_fstats[(b*16 + g0)*2 + 1], ss0);
        atomicAdd(&g_fstats[(b*16 + g0 + 2)*2    ], s1);
        atomicAdd(&g_fstats[(b*16 + g0 + 2)*2 + 1], ss1);
    }
}

// ---------------- final GN (float4) ----------------
__global__ void kFinalGN(const float* __restrict__ gng, const float* __restrict__ gnb,
                         float* __restrict__ out){
    int idx4 = blockIdx.x*256 + threadIdx.x;
    int idx = idx4*4;
    int b = idx >> 20;
    int c = (idx >> 14) & 63;
    int g = c >> 2;
    float s  = g_fstats[(b*16+g)*2];
    float ss = g_fstats[(b*16+g)*2+1];
    float mu = s * (1.f/65536.f);
    float var = ss * (1.f/65536.f) - mu*mu;
    float rs = rsqrtf(var + 1e-5f) * gng[c];
    float bb = gnb[c];
    float4 v = *(const float4*)&g_outraw[idx];
    float4 o;
    o.x = (v.x - mu)*rs + bb;
    o.y = (v.y - mu)*rs + bb;
    o.z = (v.z - mu)*rs + bb;
    o.w = (v.w - mu)*rs + bb;
    *(float4*)&out[idx] = o;
}

extern "C" void kernel_launch(void* const* d_in, const int* in_sizes, int n_in,
                              void* d_out, int out_size){
    const float* x     = (const float*)d_in[0];
    const float* offw  = (const float*)d_in[1];
    const float* offb  = (const float*)d_in[2];
    const float* gnog  = (const float*)d_in[3];
    const float* gnob  = (const float*)d_in[4];
    const float* altho = (const float*)d_in[5];
    const float* ipw   = (const float*)d_in[6];
    const float* cw    = (const float*)d_in[7];
    const float* cb    = (const float*)d_in[8];
    const float* xpw   = (const float*)d_in[9];
    const float* dtw   = (const float*)d_in[10];
    const float* dtb   = (const float*)d_in[11];
    const float* Alog  = (const float*)d_in[12];
    const float* Dp    = (const float*)d_in[13];
    const float* opw   = (const float*)d_in[14];
    const float* dscw  = (const float*)d_in[15];
    const float* dscb  = (const float*)d_in[16];
    const float* gng   = (const float*)d_in[17];
    const float* gnb   = (const float*)d_in[18];
    float* out = (float*)d_out;

    cudaFuncSetAttribute(kConvM, cudaFuncAttributeMaxDynamicSharedMemorySize, CONVM_SMEM);
    cudaFuncSetAttribute(kMamba, cudaFuncAttributeMaxDynamicSharedMemorySize, MAMBA_SMEM);
    cudaFuncSetAttribute(kDeform, cudaFuncAttributeMaxDynamicSharedMemorySize, DEF_SMEM);

    kPrep<<<dim3(512, 2, 4), dim3(32, 8)>>>(x, dscw, offw);
    kConvM<<<dim3(128, 4), 256, CONVM_SMEM>>>(offb);
    kMamba<<<dim3(NCH, 4), 288, MAMBA_SMEM>>>(gnog, gnob, ipw, cw, cb, xpw, dtw, dtb,
                                              Alog, Dp, opw, altho);
    kDeform<<<dim3(128, 4), 256, DEF_SMEM>>>(dscb);
    kFinalGN<<<4096, 256>>>(gng, gnb, out);
}

// round 16
// speedup vs baseline: 1.3472x; 1.0381x over previous
#include <cuda_runtime.h>
#include <math.h>

#define Bn   4
#define HWp  16384
#define LSEQ 16384
#define CH   256
#define NCH  64

// ---------------- tf32 mma helpers ----------------
__device__ __forceinline__ unsigned tf32cvt(float v){
    unsigned r; asm("cvt.rna.tf32.f32 %0, %1;" : "=r"(r) : "f"(v)); return r;
}
__device__ __forceinline__ void mma_tf32(float* d, unsigned a0, unsigned a1, unsigned a2, unsigned a3,
                                         unsigned b0, unsigned b1){
    asm("mma.sync.aligned.m16n8k8.row.col.f32.tf32.tf32.f32 "
        "{%0,%1,%2,%3}, {%4,%5,%6,%7}, {%8,%9}, {%0,%1,%2,%3};"
        : "+f"(d[0]), "+f"(d[1]), "+f"(d[2]), "+f"(d[3])
        : "r"(a0), "r"(a1), "r"(a2), "r"(a3), "r"(b0), "r"(b1));
}

// ---------------- scratch ----------------
__device__ float g_xT[Bn*HWp*64];        // [b][pix][c]
__device__ float g_rawoff[Bn*10*HWp];    // offset conv out, [b][co][pix]
__device__ float g_ostats[Bn*5*2];
__device__ float g_ynew[Bn*9*HWp];       // [b][k][pix]
__device__ float g_P[Bn*NCH*288];
__device__ float g_Q[Bn*NCH*288];
__device__ float g_py[Bn*9*HWp];         // [b][k][pix]
__device__ unsigned g_wAf[9*64*64];      // deform conv A, mma fragment order
__device__ unsigned g_wCf[9*8*128];      // offset conv A, mma fragment order
__device__ float g_outraw[Bn*64*HWp];
__device__ float g_fstats[Bn*16*2];
__device__ unsigned g_cnt;               // grid-barrier counter (zeroed by kPrep)

__device__ __forceinline__ float softplusf(float x){
    return x > 20.f ? x : log1pf(__expf(x));
}
__device__ __forceinline__ float siluf(float x){
    return __fdividef(x, 1.f + __expf(-x));
}
__device__ __forceinline__ float ftanh(float x){
    float xc = fminf(fmaxf(x, -15.f), 15.f);
    float e = __expf(2.f*xc);
    return __fdividef(e - 1.f, e + 1.f);
}

// ---------------- prep: transpose x + zero stats/counter + weight tf32 conversions ----------------
__global__ void kPrep(const float* __restrict__ x, const float* __restrict__ dscw,
                      const float* __restrict__ offw){
    __shared__ float tile[32][33];
    int b = blockIdx.z, c0 = blockIdx.y*32, p0 = blockIdx.x*32;
    int bid = (blockIdx.z*gridDim.y + blockIdx.y)*gridDim.x + blockIdx.x;
    int gtid = bid*256 + threadIdx.y*32 + threadIdx.x;

    if (gtid == 0) g_cnt = 0u;
    if (gtid < 36864){
        int k = gtid >> 12;
        int rem = gtid & 4095;
        int ctq = rem >> 10;
        int rem2 = rem & 1023;
        int ks = rem2 >> 7;
        int r = rem2 & 127;
        int lane = r >> 2, q = r & 3;
        int gID = lane >> 2, tig = lane & 3;
        int co = ctq*16 + gID + ((q & 1) << 3);
        int ci = ks*8 + tig + ((q >> 1) << 2);
        g_wAf[gtid] = tf32cvt(dscw[(co*64 + ci)*9 + k]);
    }
    if (gtid >= 40960 && gtid < 40960+9216){
        int idx = gtid - 40960;
        int tap = idx >> 10; int rem = idx & 1023;
        int ks = rem >> 7;   int r = rem & 127;
        int lane = r >> 2,   q = r & 3;
        int gID = lane >> 2, tig = lane & 3;
        int co = gID + 8*(q & 1);
        int ci = ks*8 + tig + 4*(q >> 1);
        int dy = tap/3, dx = tap - dy*3;
        float v = (co < 10) ? offw[((co*64+ci)*3 + dy)*3 + dx] : 0.f;
        g_wCf[idx] = tf32cvt(v);
    }
    if (gtid >= 65536 && gtid < 65536+40)  g_ostats[gtid-65536] = 0.f;
    if (gtid >= 131072 && gtid < 131072+128) g_fstats[gtid-131072] = 0.f;

    for (int i = threadIdx.y; i < 32; i += 8)
        tile[i][threadIdx.x] = x[(size_t)(b*64 + c0 + i)*HWp + p0 + threadIdx.x];
    __syncthreads();
    for (int i = threadIdx.y; i < 32; i += 8)
        g_xT[(size_t)(b*HWp + p0 + i)*64 + c0 + threadIdx.x] = tile[threadIdx.x][i];
}

// ---------------- offset conv 3x3 64->10 via tf32 mma (implicit im2col) ----------------
#define CONVM_SMEM (390*68*4)
__global__ void __launch_bounds__(256) kConvM(const float* __restrict__ offb){
    extern __shared__ unsigned su[];
    unsigned* sV = su;            // [dy*130+jp][68]
    int h = blockIdx.x, b = blockIdx.y, t = threadIdx.x;
    int wid = t >> 5, lane = t & 31, gID = lane >> 2, tig = lane & 3;
    int n0 = wid*16;

    {
        int c4 = t & 15;
        int r = t >> 4;
        int jp = r, dy = 0;
        while (r < 390){
            int gh = h - 1 + dy, gw = jp - 1;
            float4 v = make_float4(0.f, 0.f, 0.f, 0.f);
            if (gh >= 0 && gh < 128 && gw >= 0 && gw < 128)
                v = *(const float4*)&g_xT[((size_t)b*HWp + gh*128 + gw)*64 + c4*4];
            uint4 tv;
            tv.x = tf32cvt(v.x); tv.y = tf32cvt(v.y);
            tv.z = tf32cvt(v.z); tv.w = tf32cvt(v.w);
            *(uint4*)&sV[r*68 + c4*4] = tv;
            r += 16; jp += 16;
            if (jp >= 130){ jp -= 130; dy++; }
        }
    }
    __syncthreads();

    float acc[2][4];
    #pragma unroll
    for (int nt = 0; nt < 2; nt++)
        #pragma unroll
        for (int p = 0; p < 4; p++) acc[nt][p] = 0.f;

    #pragma unroll
    for (int tap = 0; tap < 9; tap++){
        int dy = tap/3, dx = tap - dy*3;
        int vbase = dy*130 + dx;
        #pragma unroll
        for (int ks = 0; ks < 8; ks++){
            int kk = ks*8;
            uint4 f = *(const uint4*)&g_wCf[((tap*8 + ks) << 7) + (lane << 2)];
            #pragma unroll
            for (int nt = 0; nt < 2; nt++){
                int j = n0 + nt*8 + gID;
                unsigned b0 = sV[(vbase + j)*68 + kk + tig];
                unsigned b1 = sV[(vbase + j)*68 + kk + tig + 4];
                mma_tf32(acc[nt], f.x, f.y, f.z, f.w, b0, b1);
            }
        }
    }

    int co0 = gID, co1 = gID + 8;
    float bias0 = offb[co0];
    float bias1 = (gID < 2) ? offb[co1] : 0.f;
    float s0 = 0.f, ss0 = 0.f, s1 = 0.f, ss1 = 0.f;
    #pragma unroll
    for (int nt = 0; nt < 2; nt++){
        float c0 = acc[nt][0] + bias0, c1 = acc[nt][1] + bias0;
        int pix = h*128 + n0 + nt*8 + tig*2;
        *(float2*)&g_rawoff[((size_t)(b*10+co0))*HWp + pix] = make_float2(c0, c1);
        s0 += c0 + c1; ss0 += c0*c0 + c1*c1;
        if (gID < 2){
            float c2 = acc[nt][2] + bias1, c3 = acc[nt][3] + bias1;
            *(float2*)&g_rawoff[((size_t)(b*10+co1))*HWp + pix] = make_float2(c2, c3);
            s1 += c2 + c3; ss1 += c2*c2 + c3*c3;
        }
    }
    #pragma unroll
    for (int m = 1; m <= 4; m <<= 1){
        s0  += __shfl_xor_sync(0xffffffffu, s0,  m);
        ss0 += __shfl_xor_sync(0xffffffffu, ss0, m);
        s1  += __shfl_xor_sync(0xffffffffu, s1,  m);
        ss1 += __shfl_xor_sync(0xffffffffu, ss1, m);
    }
    if (tig == 0 && (gID & 1) == 0){
        int g0 = gID >> 1;
        atomicAdd(&g_ostats[(b*5 + g0)*2    ], s0);
        atomicAdd(&g_ostats[(b*5 + g0)*2 + 1], ss0);
        if (gID == 0){
            atomicAdd(&g_ostats[(b*5 + 4)*2    ], s1);
            atomicAdd(&g_ostats[(b*5 + 4)*2 + 1], ss1);
        }
    }
}

// ---------------- merged mamba ----------------
__device__ __forceinline__ void comp_tv(int b, int l, const float* sMu, const float* sRs,
                                        const float* __restrict__ gnog,
                                        const float* __restrict__ gnob, float* tv){
    int tt = l & 1, r = l >> 1;
    int w = r & 127, r2 = r >> 7;
    int p = (r2*2 + tt)*128 + w;
    #pragma unroll
    for (int c = 0; c < 9; c++){
        float raw = g_rawoff[((size_t)(b*10+c))*HWp + p];
        float xn = (raw - sMu[c>>1]) * sRs[c>>1] * gnog[c] + gnob[c];
        tv[c] = ftanh(xn);
    }
}

#define MAMBA_SMEM (28257*4)
__global__ void __launch_bounds__(288, 2) kMamba(
        const float* __restrict__ gnog, const float* __restrict__ gnob,
        const float* __restrict__ ipw,  const float* __restrict__ cw,
        const float* __restrict__ cb,   const float* __restrict__ xpw,
        const float* __restrict__ dtw,  const float* __restrict__ dtb,
        const float* __restrict__ Alog, const float* __restrict__ Dp,
        const float* __restrict__ opw,  const float* __restrict__ altho){
    extern __shared__ float sm[];
    float* sXP   = sm;             // 4921 (phase A); overlaid by sYS in phase D
    float* sYS   = sm;             // 18*257
    float* sIPW  = sm + 4921;
    float* sXPW  = sm + 5245;
    float* sCW   = sm + 5839;
    float* sCB   = sm + 5911;
    float* sDTW  = sm + 5929;
    float* sDTB  = sm + 5947;
    float* sMu   = sm + 5965;
    float* sRs   = sm + 5970;
    float* sDT   = sm + 5975;
    float* sXI   = sm + 10601;
    float* sB    = sm + 15227;
    float* sC    = sm + 19339;
    float* sGate = sm + 23451;
    float* sOPW  = sm + 28077;
    float* sDP   = sm + 28239;
    int b = blockIdx.y, c = blockIdx.x, l0 = c*CH, t = threadIdx.x;

    for (int idx = t; idx < 324; idx += 288) sIPW[idx] = ipw[idx];
    for (int idx = t; idx < 594; idx += 288) sXPW[idx] = xpw[idx];
    if (t < 72) sCW[t] = cw[t];
    if (t < 18){ sCB[t] = cb[t]; sDTW[t] = dtw[t]; sDTB[t] = dtb[t]; }
    if (t >= 32 && t < 194) sOPW[t-32] = opw[t-32];
    if (t >= 224 && t < 242) sDP[t-224] = Dp[t-224];
    if (t < 5){
        float s  = g_ostats[(b*5+t)*2];
        float ss = g_ostats[(b*5+t)*2+1];
        float mu = s * (1.f/32768.f);
        float var = ss * (1.f/32768.f) - mu*mu;
        sMu[t] = mu;
        sRs[t] = rsqrtf(var + 1e-5f);
    }
    __syncthreads();

    if (t < CH){
        int l = l0 + t;
        float tv[9];
        comp_tv(b, l, sMu, sRs, gnog, gnob, tv);

        float cum[9];
        cum[4] = 0.f;
        cum[5] = tv[5]; cum[6] = cum[5]+tv[6]; cum[7] = cum[6]+tv[7]; cum[8] = cum[7]+tv[8];
        cum[3] = tv[3]; cum[2] = cum[3]+tv[2]; cum[1] = cum[2]+tv[1]; cum[0] = cum[1]+tv[0];

        int tt = l & 1, r = l >> 1;
        int w = r & 127, r2 = r >> 7;
        int h = r2*2 + tt, p = h*128 + w;
        #pragma unroll
        for (int k = 0; k < 9; k++)
            g_ynew[((size_t)(b*9+k))*HWp + p] = (float)h + cum[k];

        #pragma unroll
        for (int n = 0; n < 18; n++){
            float v = 0.f;
            #pragma unroll
            for (int m = 0; m < 9; m++) v += tv[m]*sIPW[n*9+m];
            sXP[(t+3)*19 + n] = v;
        }
        #pragma unroll
        for (int n = 0; n < 18; n++){
            float z = 0.f;
            #pragma unroll
            for (int m = 0; m < 9; m++) z += tv[m]*sIPW[(18+n)*9+m];
            sGate[n*257 + t] = siluf(z);
        }
    } else if (t < CH+3){
        int bi = t - CH;
        int l2 = l0 - 3 + bi;
        if (l2 >= 0){
            float tv2[9];
            comp_tv(b, l2, sMu, sRs, gnog, gnob, tv2);
            #pragma unroll
            for (int n = 0; n < 18; n++){
                float v = 0.f;
                #pragma unroll
                for (int m = 0; m < 9; m++) v += tv2[m]*sIPW[n*9+m];
                sXP[bi*19 + n] = v;
            }
        } else {
            #pragma unroll
            for (int n = 0; n < 18; n++) sXP[bi*19 + n] = 0.f;
        }
    }
    __syncthreads();

    if (t < CH){
        float xi[18];
        #pragma unroll
        for (int d = 0; d < 18; d++){
            float xc = sCB[d];
            #pragma unroll
            for (int j = 0; j < 4; j++) xc += sCW[d*4+j]*sXP[(t+j)*19 + d];
            xi[d] = siluf(xc);
        }
        float dtr = 0.f;
        #pragma unroll
        for (int d = 0; d < 18; d++) dtr += xi[d]*sXPW[d];
        #pragma unroll
        for (int s = 0; s < 16; s++){
            float bv = 0.f, cv = 0.f;
            #pragma unroll
            for (int d = 0; d < 18; d++){
                bv += xi[d]*sXPW[(1+s)*18 + d];
                cv += xi[d]*sXPW[(17+s)*18 + d];
            }
            sB[s*257 + t] = bv;
            sC[s*257 + t] = cv;
        }
        #pragma unroll
        for (int d = 0; d < 18; d++){
            float a = dtr*sDTW[d] + sDTB[d];
            sDT[d*257 + t] = softplusf(a);
            sXI[d*257 + t] = xi[d];
        }
    }
    __syncthreads();

    int d = t / 16, s = t % 16;
    float a = -expf(Alog[d*16+s]);
    {
        float p = 1.f, q = 0.f;
        for (int i = 0; i < CH; i++){
            float dt = sDT[d*257+i];
            float da = __expf(dt*a);
            q = da*q + dt*sB[s*257+i]*sXI[d*257+i];
            p *= da;
        }
        g_P[(b*NCH+c)*288 + t] = p;
        g_Q[(b*NCH+c)*288 + t] = q;
    }
    __syncthreads();
    __threadfence();
    if (t == 0) atomicAdd(&g_cnt, 1u);

    if (t == 0){
        while (*((volatile unsigned*)&g_cnt) < (unsigned)(NCH*Bn)) __nanosleep(64);
    }
    __syncthreads();
    __threadfence();

    float h = 0.f;
    for (int cc = 0; cc < c; cc++){
        float pp = __ldcg(&g_P[(b*NCH+cc)*288 + t]);
        float qq = __ldcg(&g_Q[(b*NCH+cc)*288 + t]);
        h = pp*h + qq;
    }

    for (int i = 0; i < CH; i++){
        float dt = sDT[d*257+i];
        float da = __expf(dt*a);
        h = da*h + dt*sB[s*257+i]*sXI[d*257+i];
        float v = h * sC[s*257+i];
        v += __shfl_xor_sync(0xffffffffu, v, 1);
        v += __shfl_xor_sync(0xffffffffu, v, 2);
        v += __shfl_xor_sync(0xffffffffu, v, 4);
        v += __shfl_xor_sync(0xffffffffu, v, 8);
        if ((t & 15) == 0) sYS[d*257+i] = v;
    }
    __syncthreads();

    if (t < CH){
        int l = l0 + t;
        float wgt = fmaxf(softplusf(altho[0]), 0.01f);
        float ym[9];
        #pragma unroll
        for (int m = 0; m < 9; m++) ym[m] = 0.f;
        #pragma unroll
        for (int dd = 0; dd < 18; dd++){
            float yv = (sYS[dd*257+t] + sDP[dd]*sXI[dd*257+t]) * sGate[dd*257+t];
            #pragma unroll
            for (int m = 0; m < 9; m++) ym[m] += yv * sOPW[m*18+dd];
        }
        int tt = l & 1, r = l >> 1;
        int w = r & 127, h2 = r >> 7;
        int pix = (h2*2 + tt)*128 + w;
        #pragma unroll
        for (int m = 0; m < 9; m++){
            float py = wgt*ym[m] + g_ynew[((size_t)(b*9+m))*HWp + pix];
            py = fminf(fmaxf(py, 0.f), 127.f);
            g_py[((size_t)(b*9+m))*HWp + pix] = py;
        }
    }
}

// ---------------- deformable gather + tf32 tensor-core contraction + GN stats ----------------
// sV stride 72, channel-permuted: pos(c) = (c&~7) + ((c&7)<4 ? 2(c&7) : 2(c&7)-7)
// -> B fragment (kk+tig, kk+tig+4) = one LDS.64 at word kk+2*tig (conflict-free:
// bank-pair 4*gID+tig distinct per half-warp). Gather: lane handles channels
// (2lane, 2lane+1) via LDG.64 pairs; STS positions {0,1,4,5,...}+kk distinct.
#define DEF_SMEM (128*72*4)
__global__ void __launch_bounds__(256) kDeform(const float* __restrict__ dscb){
    extern __shared__ unsigned sV[];    // [pix][perm ci] stride 72
    int i = blockIdx.x, b = blockIdx.y, t = threadIdx.x;
    int wid = t >> 5, lane = t & 31;
    int gID = lane >> 2, tig = lane & 3;
    int ctq = wid & 3, ct = ctq*16;
    int pt = (wid >> 2)*64;

    int ch0 = 2*lane;
    int r0 = ch0 & 7,  k0 = ch0 & ~7;
    int r1 = (ch0+1) & 7, k1 = (ch0+1) & ~7;
    int pos0 = k0 + ((r0 < 4) ? 2*r0 : 2*r0 - 7);
    int pos1 = k1 + ((r1 < 4) ? 2*r1 : 2*r1 - 7);
    const float* bbase = &g_xT[(size_t)b*HWp*64];
    const float* pybase = &g_py[(size_t)b*9*HWp + i*128];

    float acc[8][4];
    #pragma unroll
    for (int nt = 0; nt < 8; nt++)
        #pragma unroll
        for (int p = 0; p < 4; p++) acc[nt][p] = 0.f;

    for (int k = 0; k < 9; k++){
        int p0 = wid*16;
        #pragma unroll
        for (int pp = 0; pp < 16; pp++){
            int j = p0 + pp;
            float pyv = pybase[k*HWp + j];
            float fy0 = floorf(pyv);
            int y0 = (int)fy0;
            float wy = pyv - fy0;
            float wy0 = 1.f - wy;
            int y1 = min(y0 + 1, 127);
            int xc = min(max(j + k - 4, 0), 127);
            int off = (xc << 6) + ch0;
            float2 v0 = *(const float2*)(bbase + (y0 << 13) + off);
            float2 v1 = *(const float2*)(bbase + (y1 << 13) + off);
            float vL = v0.x*wy0 + v1.x*wy;
            float vH = v0.y*wy0 + v1.y*wy;
            sV[j*72 + pos0] = tf32cvt(vL);
            sV[j*72 + pos1] = tf32cvt(vH);
        }
        __syncthreads();

        #pragma unroll
        for (int ks = 0; ks < 8; ks++){
            int kk = ks*8;
            uint4 f = *(const uint4*)&g_wAf[((((k*4 + ctq)*8) + ks) << 7) + (lane << 2)];
            #pragma unroll
            for (int nt = 0; nt < 8; nt++){
                int n0 = pt + nt*8;
                uint2 bv = *(const uint2*)&sV[(n0+gID)*72 + kk + 2*tig];
                mma_tf32(acc[nt], f.x, f.y, f.z, f.w, bv.x, bv.y);
            }
        }
        __syncthreads();
    }

    int co0 = ct + gID, co1 = ct + gID + 8;
    float bias0 = dscb[co0], bias1 = dscb[co1];
    float s0 = 0.f, ss0 = 0.f, s1 = 0.f, ss1 = 0.f;
    #pragma unroll
    for (int nt = 0; nt < 8; nt++){
        float c0 = acc[nt][0] + bias0, c1 = acc[nt][1] + bias0;
        float c2 = acc[nt][2] + bias1, c3 = acc[nt][3] + bias1;
        size_t pix = (size_t)i*128 + pt + nt*8 + tig*2;
        *(float2*)&g_outraw[((size_t)(b*64+co0))*HWp + pix] = make_float2(c0, c1);
        *(float2*)&g_outraw[((size_t)(b*64+co1))*HWp + pix] = make_float2(c2, c3);
        s0 += c0 + c1; ss0 += c0*c0 + c1*c1;
        s1 += c2 + c3; ss1 += c2*c2 + c3*c3;
    }
    #pragma unroll
    for (int m = 1; m <= 8; m <<= 1){
        s0  += __shfl_xor_sync(0xffffffffu, s0,  m);
        ss0 += __shfl_xor_sync(0xffffffffu, ss0, m);
        s1  += __shfl_xor_sync(0xffffffffu, s1,  m);
        ss1 += __shfl_xor_sync(0xffffffffu, ss1, m);
    }
    if ((lane & 15) == 0){
        int g0 = (ct >> 2) + (lane >> 4);
        atomicAdd(&g_fstats[(b*16 + g0)*2    ], s0);
        atomicAdd(&g_fstats[(b*16 + g0)*2 + 1], ss0);
        atomicAdd(&g_fstats[(b*16 + g0 + 2)*2    ], s1);
        atomicAdd(&g_fstats[(b*16 + g0 + 2)*2 + 1], ss1);
    }
}

// ---------------- final GN (float4) ----------------
__global__ void kFinalGN(const float* __restrict__ gng, const float* __restrict__ gnb,
                         float* __restrict__ out){
    int idx4 = blockIdx.x*256 + threadIdx.x;
    int idx = idx4*4;
    int b = idx >> 20;
    int c = (idx >> 14) & 63;
    int g = c >> 2;
    float s  = g_fstats[(b*16+g)*2];
    float ss = g_fstats[(b*16+g)*2+1];
    float mu = s * (1.f/65536.f);
    float var = ss * (1.f/65536.f) - mu*mu;
    float rs = rsqrtf(var + 1e-5f) * gng[c];
    float bb = gnb[c];
    float4 v = *(const float4*)&g_outraw[idx];
    float4 o;
    o.x = (v.x - mu)*rs + bb;
    o.y = (v.y - mu)*rs + bb;
    o.z = (v.z - mu)*rs + bb;
    o.w = (v.w - mu)*rs + bb;
    *(float4*)&out[idx] = o;
}

extern "C" void kernel_launch(void* const* d_in, const int* in_sizes, int n_in,
                              void* d_out, int out_size){
    const float* x     = (const float*)d_in[0];
    const float* offw  = (const float*)d_in[1];
    const float* offb  = (const float*)d_in[2];
    const float* gnog  = (const float*)d_in[3];
    const float* gnob  = (const float*)d_in[4];
    const float* altho = (const float*)d_in[5];
    const float* ipw   = (const float*)d_in[6];
    const float* cw    = (const float*)d_in[7];
    const float* cb    = (const float*)d_in[8];
    const float* xpw   = (const float*)d_in[9];
    const float* dtw   = (const float*)d_in[10];
    const float* dtb   = (const float*)d_in[11];
    const float* Alog  = (const float*)d_in[12];
    const float* Dp    = (const float*)d_in[13];
    const float* opw   = (const float*)d_in[14];
    const float* dscw  = (const float*)d_in[15];
    const float* dscb  = (const float*)d_in[16];
    const float* gng   = (const float*)d_in[17];
    const float* gnb   = (const float*)d_in[18];
    float* out = (float*)d_out;

    cudaFuncSetAttribute(kConvM, cudaFuncAttributeMaxDynamicSharedMemorySize, CONVM_SMEM);
    cudaFuncSetAttribute(kMamba, cudaFuncAttributeMaxDynamicSharedMemorySize, MAMBA_SMEM);
    cudaFuncSetAttribute(kDeform, cudaFuncAttributeMaxDynamicSharedMemorySize, DEF_SMEM);

    kPrep<<<dim3(512, 2, 4), dim3(32, 8)>>>(x, dscw, offw);
    kConvM<<<dim3(128, 4), 256, CONVM_SMEM>>>(offb);
    kMamba<<<dim3(NCH, 4), 288, MAMBA_SMEM>>>(gnog, gnob, ipw, cw, cb, xpw, dtw, dtb,
                                              Alog, Dp, opw, altho);
    kDeform<<<dim3(128, 4), 256, DEF_SMEM>>>(dscb);
    kFinalGN<<<4096, 256>>>(gng, gnb, out);
}